// round 14
// baseline (speedup 1.0000x reference)
#include <cuda_runtime.h>
#include <cuda_fp16.h>
#include <cstdint>

// ---------------- problem constants ----------------
#define HD   256      // hidden / embedding dim
#define G3   768      // 3*H gate dim
#define VOCAB 30000
#define NW   2048     // word-level sequences (B*R*S)
#define TW   32       // word-level timesteps (W)
#define NS   128      // sentence-level sequences (B*R)
#define TS   16       // sentence-level timesteps (S)
#define NR   8        // review-level sequences (B)
#define TR   16       // review-level timesteps (R)

#define WH   264      // Wres row stride in halfs (528B -> conflict-free ldsm)
#define HS2  40       // gemm A/B tile row stride in halfs
#define HS3  72       // scan H chunk row stride in halfs (64 data + 8 pad)

// scan smem (halfs): Wres[96*WH] + Hsm[2][128][HS3]
#define SCAN_SMEM_BYTES ((96*WH + 2*128*HS3) * 2)
// gemm smem (halfs): As[2][128][HS2] + Bs[2][64][HS2]
#define GEMM_SMEM_BYTES ((2*128*HS2 + 2*64*HS2) * 2)

#define NBAR 36       // word 0..31, sentence 32..33, review 34..35
#define BPAD 32       // barrier slot padding (128B)

// ---------------- scratch (static device globals; no runtime alloc) ----------------
__device__ __half g_PV [(size_t)2*VOCAB*G3];       // projected vocab per dir (fp16)
__device__ __half g_GXs[(size_t)2*NS*TS*G3];       // sentence-level gx (fp16)
__device__ __half g_GXr[(size_t)2*NR*TR*G3];       // review-level gx (fp16)
__device__ __half g_EH [(size_t)VOCAB*HD];         // emb in fp16
__device__ __half g_WIH[(size_t)2*G3*HD];          // word Wih in fp16
__device__ float  g_Hw [2][(size_t)2*NW*HD];       // ping-pong hidden, word
__device__ float  g_Hs [2][(size_t)2*NS*HD];       // sentence
__device__ float  g_Hr [2][(size_t)2*NR*HD];       // review

// grid-barrier state: one padded slot per (scan, dir, rowgroup)
__device__ unsigned g_cnt[NBAR * BPAD];
__device__ volatile unsigned g_phase[NBAR * BPAD];

// ---------------- helpers ----------------
__device__ __forceinline__ float fsigm(float x) {
    float e = __expf(-x);
    return __fdividef(1.f, 1.f + e);
}
__device__ __forceinline__ float ftanh(float x) {
    float ax = fabsf(x);
    float e = __expf(-2.f * ax);
    float r = __fdividef(1.f - e, 1.f + e);
    return copysignf(r, x);
}

__device__ __forceinline__ unsigned f2h2u(float lo, float hi) {
    __half2 h = __floats2half2_rn(lo, hi);
    return *(unsigned*)&h;
}

__device__ __forceinline__ void mma16(float* d,
                                      unsigned a0, unsigned a1, unsigned a2, unsigned a3,
                                      unsigned b0, unsigned b1) {
    asm volatile(
        "mma.sync.aligned.m16n8k16.row.col.f32.f16.f16.f32 "
        "{%0,%1,%2,%3},{%4,%5,%6,%7},{%8,%9},{%0,%1,%2,%3};"
        : "+f"(d[0]), "+f"(d[1]), "+f"(d[2]), "+f"(d[3])
        : "r"(a0), "r"(a1), "r"(a2), "r"(a3), "r"(b0), "r"(b1));
}

__device__ __forceinline__ void ldsm4(unsigned& r0, unsigned& r1, unsigned& r2, unsigned& r3,
                                      unsigned addr) {
    asm volatile("ldmatrix.sync.aligned.m8n8.x4.shared.b16 {%0,%1,%2,%3}, [%4];"
                 : "=r"(r0), "=r"(r1), "=r"(r2), "=r"(r3) : "r"(addr));
}
__device__ __forceinline__ void ldsm2(unsigned& r0, unsigned& r1, unsigned addr) {
    asm volatile("ldmatrix.sync.aligned.m8n8.x2.shared.b16 {%0,%1}, [%2];"
                 : "=r"(r0), "=r"(r1) : "r"(addr));
}

// named barrier over 128 threads (4 warps), ids 1..2
__device__ __forceinline__ void barhalf(int id) {
    asm volatile("bar.sync %0, 128;" :: "r"(id) : "memory");
}

__global__ void kinit_bar() {
    for (int i = threadIdx.x; i < NBAR * BPAD; i += blockDim.x) {
        g_cnt[i] = 0; g_phase[i] = 0;
    }
}

// fp32 -> fp16 bulk convert
__global__ void cvt16(const float* __restrict__ src, __half* __restrict__ dst, size_t n) {
    size_t i = ((size_t)blockIdx.x * blockDim.x + threadIdx.x) * 2;
    size_t stride = (size_t)gridDim.x * blockDim.x * 2;
    for (; i < n; i += stride) {
        float2 v = *(const float2*)(src + i);
        *(__half2*)(dst + i) = __floats2half2_rn(v.x, v.y);
    }
}

// software grid barrier over an nCTA-member group (slot = id*BPAD)
__device__ __forceinline__ void gbar(int id, unsigned nCTA, unsigned target) {
    __syncthreads();
    if (threadIdx.x == 0) {
        __threadfence();
        unsigned* cnt = &g_cnt[id * BPAD];
        unsigned old = atomicAdd(cnt, 1u);
        if (old == nCTA - 1u) {
            *cnt = 0u;
            __threadfence();
            g_phase[id * BPAD] = target;
        } else {
            while (g_phase[id * BPAD] < target) __nanosleep(32);
        }
        __threadfence();
    }
    __syncthreads();
}

// ---------------- FP16-input GEMM: C[d][M,768] = A[M,256] @ W[d][768,256]^T + bias[d] ----------------
// A and W already fp16. CTA 128x64, warps 4m x 2n, warp tile 32x32; fp16 output.
__global__ __launch_bounds__(256, 2)
void gemm_proj_h(const __half* __restrict__ A, int M,
                 const __half* __restrict__ W, const float* __restrict__ bias,
                 __half* __restrict__ C)
{
    extern __shared__ __half gsm[];
    __half* As = gsm;                   // [2][128][HS2]
    __half* Bs = gsm + 2 * 128 * HS2;   // [2][64][HS2]

    int d = blockIdx.z;
    const __half* Wd = W    + (size_t)d * G3 * HD;
    const float*  bd = bias + (size_t)d * G3;
    __half*       Cd = C    + (size_t)d * M * G3;

    int m0 = blockIdx.x * 128;
    int n0 = blockIdx.y * 64;

    int tid = threadIdx.x, lane = tid & 31, wid = tid >> 5;
    int wm = wid & 3, wn = wid >> 2;
    int RB = wm * 32, CB = wn * 32;
    int g = lane >> 2, c = lane & 3;

    int l7 = lane & 7, ts = lane >> 3;
    unsigned sAs = (unsigned)__cvta_generic_to_shared(As);
    unsigned sBs = (unsigned)__cvta_generic_to_shared(Bs);

    unsigned aAddr[2];
#pragma unroll
    for (int mt = 0; mt < 2; ++mt)
        aAddr[mt] = sAs + (unsigned)(((RB + mt * 16 + l7 + (ts & 1) * 8) * HS2
                                      + (ts >> 1) * 8) * 2);
    unsigned bAddr[2];
#pragma unroll
    for (int p = 0; p < 2; ++p)
        bAddr[p] = sBs + (unsigned)(((CB + (2 * p + (ts >> 1)) * 8 + l7) * HS2
                                     + (ts & 1) * 8) * 2);

    float acc[2][4][4];
#pragma unroll
    for (int i = 0; i < 2; ++i)
#pragma unroll
        for (int j = 0; j < 4; ++j)
#pragma unroll
            for (int k = 0; k < 4; ++k) acc[i][j][k] = 0.f;

    int lr = tid >> 3, lq = tid & 7;

    uint2 pa[4], pw[2];
#pragma unroll
    for (int it = 0; it < 4; ++it) {
        int r = lr + it * 32;
        pa[it] = make_uint2(0u, 0u);
        if (m0 + r < M) pa[it] = *(const uint2*)(A + (size_t)(m0 + r) * HD + lq * 4);
    }
#pragma unroll
    for (int it = 0; it < 2; ++it) {
        int r = lr + it * 32;
        pw[it] = *(const uint2*)(Wd + (size_t)(n0 + r) * HD + lq * 4);
    }
#pragma unroll
    for (int it = 0; it < 4; ++it) {
        int r = lr + it * 32;
        *(uint2*)(As + (size_t)r * HS2 + lq * 4) = pa[it];
    }
#pragma unroll
    for (int it = 0; it < 2; ++it) {
        int r = lr + it * 32;
        *(uint2*)(Bs + (size_t)r * HS2 + lq * 4) = pw[it];
    }
    __syncthreads();

    for (int k0i = 0; k0i < 8; ++k0i) {
        int cur = k0i & 1;
        if (k0i < 7) {
            int k0 = (k0i + 1) * 32;
#pragma unroll
            for (int it = 0; it < 4; ++it) {
                int r = lr + it * 32;
                pa[it] = make_uint2(0u, 0u);
                if (m0 + r < M) pa[it] = *(const uint2*)(A + (size_t)(m0 + r) * HD + k0 + lq * 4);
            }
#pragma unroll
            for (int it = 0; it < 2; ++it) {
                int r = lr + it * 32;
                pw[it] = *(const uint2*)(Wd + (size_t)(n0 + r) * HD + k0 + lq * 4);
            }
        }

        unsigned aBuf = (unsigned)(cur * 128 * HS2 * 2);
        unsigned bBuf = (unsigned)(cur * 64 * HS2 * 2);
#pragma unroll
        for (int ks = 0; ks < 2; ++ks) {
            unsigned kbo = (unsigned)(ks * 32);
            unsigned a[2][4];
#pragma unroll
            for (int mt = 0; mt < 2; ++mt)
                ldsm4(a[mt][0], a[mt][1], a[mt][2], a[mt][3], aAddr[mt] + aBuf + kbo);
            unsigned b[4][2];
#pragma unroll
            for (int p = 0; p < 2; ++p)
                ldsm4(b[2*p][0], b[2*p][1], b[2*p+1][0], b[2*p+1][1], bAddr[p] + bBuf + kbo);
#pragma unroll
            for (int nt = 0; nt < 4; ++nt)
#pragma unroll
                for (int mt = 0; mt < 2; ++mt)
                    mma16(acc[mt][nt], a[mt][0], a[mt][1], a[mt][2], a[mt][3],
                          b[nt][0], b[nt][1]);
        }

        if (k0i < 7) {
            __half* An = As + (size_t)(cur ^ 1) * 128 * HS2;
            __half* Bn = Bs + (size_t)(cur ^ 1) * 64 * HS2;
#pragma unroll
            for (int it = 0; it < 4; ++it) {
                int r = lr + it * 32;
                *(uint2*)(An + (size_t)r * HS2 + lq * 4) = pa[it];
            }
#pragma unroll
            for (int it = 0; it < 2; ++it) {
                int r = lr + it * 32;
                *(uint2*)(Bn + (size_t)r * HS2 + lq * 4) = pw[it];
            }
        }
        __syncthreads();
    }

#pragma unroll
    for (int nt = 0; nt < 4; ++nt) {
        int col = n0 + CB + nt * 8 + 2 * c;
        float2 bb = *(const float2*)(bd + col);
#pragma unroll
        for (int mt = 0; mt < 2; ++mt) {
            int row0 = m0 + RB + mt * 16 + g;
            if (row0 < M)
                *(__half2*)(Cd + (size_t)row0 * G3 + col) =
                    __floats2half2_rn(acc[mt][nt][0] + bb.x, acc[mt][nt][1] + bb.y);
            int row1 = row0 + 8;
            if (row1 < M)
                *(__half2*)(Cd + (size_t)row1 * G3 + col) =
                    __floats2half2_rn(acc[mt][nt][2] + bb.x, acc[mt][nt][3] + bb.y);
        }
    }
}

// ---------------- FP32-input GEMM (fused A+A2): C fp16 ----------------
__global__ __launch_bounds__(256, 2)
void gemm_proj_mma(const float* __restrict__ A, const float* __restrict__ A2, int M,
                   const float* __restrict__ W, const float* __restrict__ bias,
                   __half* __restrict__ C)
{
    extern __shared__ __half gsm[];
    __half* As = gsm;                   // [2][128][HS2]
    __half* Bs = gsm + 2 * 128 * HS2;   // [2][64][HS2]

    int d = blockIdx.z;
    const float* Wd = W    + (size_t)d * G3 * HD;
    const float* bd = bias + (size_t)d * G3;
    __half*      Cd = C    + (size_t)d * M * G3;

    int m0 = blockIdx.x * 128;
    int n0 = blockIdx.y * 64;

    int tid = threadIdx.x, lane = tid & 31, wid = tid >> 5;
    int wm = wid & 3, wn = wid >> 2;
    int RB = wm * 32, CB = wn * 32;
    int g = lane >> 2, c = lane & 3;

    int l7 = lane & 7, ts = lane >> 3;
    unsigned sAs = (unsigned)__cvta_generic_to_shared(As);
    unsigned sBs = (unsigned)__cvta_generic_to_shared(Bs);

    unsigned aAddr[2];
#pragma unroll
    for (int mt = 0; mt < 2; ++mt)
        aAddr[mt] = sAs + (unsigned)(((RB + mt * 16 + l7 + (ts & 1) * 8) * HS2
                                      + (ts >> 1) * 8) * 2);
    unsigned bAddr[2];
#pragma unroll
    for (int p = 0; p < 2; ++p)
        bAddr[p] = sBs + (unsigned)(((CB + (2 * p + (ts >> 1)) * 8 + l7) * HS2
                                     + (ts & 1) * 8) * 2);

    float acc[2][4][4];
#pragma unroll
    for (int i = 0; i < 2; ++i)
#pragma unroll
        for (int j = 0; j < 4; ++j)
#pragma unroll
            for (int k = 0; k < 4; ++k) acc[i][j][k] = 0.f;

    int lr = tid >> 3, lq = tid & 7;

    float4 pa[4], pw[2];
#pragma unroll
    for (int it = 0; it < 4; ++it) {
        int r = lr + it * 32;
        pa[it] = make_float4(0.f, 0.f, 0.f, 0.f);
        if (m0 + r < M) {
            size_t off = (size_t)(m0 + r) * HD + lq * 4;
            pa[it] = *(const float4*)(A + off);
            if (A2) {
                float4 b = *(const float4*)(A2 + off);
                pa[it].x += b.x; pa[it].y += b.y; pa[it].z += b.z; pa[it].w += b.w;
            }
        }
    }
#pragma unroll
    for (int it = 0; it < 2; ++it) {
        int r = lr + it * 32;
        pw[it] = *(const float4*)(Wd + (size_t)(n0 + r) * HD + lq * 4);
    }
#pragma unroll
    for (int it = 0; it < 4; ++it) {
        int r = lr + it * 32;
        *(uint2*)(As + (size_t)r * HS2 + lq * 4) =
            make_uint2(f2h2u(pa[it].x, pa[it].y), f2h2u(pa[it].z, pa[it].w));
    }
#pragma unroll
    for (int it = 0; it < 2; ++it) {
        int r = lr + it * 32;
        *(uint2*)(Bs + (size_t)r * HS2 + lq * 4) =
            make_uint2(f2h2u(pw[it].x, pw[it].y), f2h2u(pw[it].z, pw[it].w));
    }
    __syncthreads();

    for (int k0i = 0; k0i < 8; ++k0i) {
        int cur = k0i & 1;
        if (k0i < 7) {
            int k0 = (k0i + 1) * 32;
#pragma unroll
            for (int it = 0; it < 4; ++it) {
                int r = lr + it * 32;
                pa[it] = make_float4(0.f, 0.f, 0.f, 0.f);
                if (m0 + r < M) {
                    size_t off = (size_t)(m0 + r) * HD + k0 + lq * 4;
                    pa[it] = *(const float4*)(A + off);
                    if (A2) {
                        float4 b = *(const float4*)(A2 + off);
                        pa[it].x += b.x; pa[it].y += b.y; pa[it].z += b.z; pa[it].w += b.w;
                    }
                }
            }
#pragma unroll
            for (int it = 0; it < 2; ++it) {
                int r = lr + it * 32;
                pw[it] = *(const float4*)(Wd + (size_t)(n0 + r) * HD + k0 + lq * 4);
            }
        }

        unsigned aBuf = (unsigned)(cur * 128 * HS2 * 2);
        unsigned bBuf = (unsigned)(cur * 64 * HS2 * 2);
#pragma unroll
        for (int ks = 0; ks < 2; ++ks) {
            unsigned kbo = (unsigned)(ks * 32);
            unsigned a[2][4];
#pragma unroll
            for (int mt = 0; mt < 2; ++mt)
                ldsm4(a[mt][0], a[mt][1], a[mt][2], a[mt][3], aAddr[mt] + aBuf + kbo);
            unsigned b[4][2];
#pragma unroll
            for (int p = 0; p < 2; ++p)
                ldsm4(b[2*p][0], b[2*p][1], b[2*p+1][0], b[2*p+1][1], bAddr[p] + bBuf + kbo);
#pragma unroll
            for (int nt = 0; nt < 4; ++nt)
#pragma unroll
                for (int mt = 0; mt < 2; ++mt)
                    mma16(acc[mt][nt], a[mt][0], a[mt][1], a[mt][2], a[mt][3],
                          b[nt][0], b[nt][1]);
        }

        if (k0i < 7) {
            __half* An = As + (size_t)(cur ^ 1) * 128 * HS2;
            __half* Bn = Bs + (size_t)(cur ^ 1) * 64 * HS2;
#pragma unroll
            for (int it = 0; it < 4; ++it) {
                int r = lr + it * 32;
                *(uint2*)(An + (size_t)r * HS2 + lq * 4) =
                    make_uint2(f2h2u(pa[it].x, pa[it].y), f2h2u(pa[it].z, pa[it].w));
            }
#pragma unroll
            for (int it = 0; it < 2; ++it) {
                int r = lr + it * 32;
                *(uint2*)(Bn + (size_t)r * HS2 + lq * 4) =
                    make_uint2(f2h2u(pw[it].x, pw[it].y), f2h2u(pw[it].z, pw[it].w));
            }
        }
        __syncthreads();
    }

#pragma unroll
    for (int nt = 0; nt < 4; ++nt) {
        int col = n0 + CB + nt * 8 + 2 * c;
        float2 bb = *(const float2*)(bd + col);
#pragma unroll
        for (int mt = 0; mt < 2; ++mt) {
            int row0 = m0 + RB + mt * 16 + g;
            if (row0 < M)
                *(__half2*)(Cd + (size_t)row0 * G3 + col) =
                    __floats2half2_rn(acc[mt][nt][0] + bb.x, acc[mt][nt][1] + bb.y);
            int row1 = row0 + 8;
            if (row1 < M)
                *(__half2*)(Cd + (size_t)row1 * G3 + col) =
                    __floats2half2_rn(acc[mt][nt][2] + bb.x, acc[mt][nt][3] + bb.y);
        }
    }
}

// ---------------- persistent fused GRU scan (fp16 MMA, 128x32 tile, 64-k chunks) ----------------
// CTA: 128 rows x 32 j-cols x 3 gates; warps 2m x 4n (warp tile 64x8x3).
// W resident fp16 (96 rows); H staged fp16 double-buffered in 64-k chunks:
// 4 named barriers per step. Rowgroup grid barrier couples gridDim.y CTAs.
__global__ __launch_bounds__(256, 2)
void gru_scan(float* __restrict__ H0, float* __restrict__ H1,
              const float* __restrict__ Whh,    // [2][768][256]
              const float* __restrict__ bhh,    // [2][768]
              const __half* __restrict__ GX,    // [2][N*T][768] or nullptr
              const __half* __restrict__ PV,    // [2][VOCAB][768] or nullptr
              const int*   __restrict__ tok,    // tokens or nullptr
              int N, int T, int barBase)
{
    extern __shared__ __half smemh[];
    __half* Wres = smemh;                        // [96][WH] rows: gt*32 + j
    __half* Hsm  = smemh + 96 * WH;              // [2][128][HS3]

    int d  = blockIdx.z;
    int n0 = blockIdx.x * 128;
    int j0 = blockIdx.y * 32;
    int bid = barBase + d * gridDim.x + blockIdx.x;

    const float* Wd = Whh + (size_t)d * G3 * HD;

    int tid = threadIdx.x, lane = tid & 31, wid = tid >> 5;
    int wm = wid & 1, wn = wid >> 1;
    int RB = wm * 64, CB = wn * 8;
    int g = lane >> 2, c = lane & 3;

    // ---- load resident W slice (fp16 RN once): 96 rows x 256 cols ----
    for (int idx = tid; idx < 96 * 64; idx += 256) {
        int row = idx >> 6;
        int c4  = idx & 63;
        int gt = row >> 5, j = row & 31;
        float4 v = *(const float4*)(Wd + (size_t)(gt * 256 + j0 + j) * HD + c4 * 4);
        *(uint2*)(Wres + (size_t)row * WH + c4 * 4) =
            make_uint2(f2h2u(v.x, v.y), f2h2u(v.z, v.w));
    }
    __syncthreads();

    int l7 = lane & 7, ts = lane >> 3;
    unsigned sH = (unsigned)__cvta_generic_to_shared(Hsm);
    unsigned sW = (unsigned)__cvta_generic_to_shared(Wres);

    unsigned aAddr[4];
#pragma unroll
    for (int mt = 0; mt < 4; ++mt)
        aAddr[mt] = sH + (unsigned)(((RB + mt * 16 + l7 + (ts & 1) * 8) * HS3
                                     + (ts >> 1) * 8) * 2);
    unsigned bAddr01 = sW + (unsigned)((((ts >> 1) * 32 + CB + l7) * WH + (ts & 1) * 8) * 2);
    unsigned bAddr2  = sW + (unsigned)(((64 + CB + l7) * WH + (ts & 1) * 8) * 2);

    bool is64 = false;
    if (tok) is64 = (tok[1] == 0) & (tok[3] == 0) & (tok[5] == 0) & (tok[7] == 0);

    int cc = j0 + CB + 2 * c;
    float2 br2 = *(const float2*)(bhh + (size_t)d * G3 + cc);
    float2 bz2 = *(const float2*)(bhh + (size_t)d * G3 + 256 + cc);
    float2 bn2 = *(const float2*)(bhh + (size_t)d * G3 + 512 + cc);

    // staging: wm-group (128 threads) stages rows [wm*64, +64), 64 halfs/chunk,
    // 4 iters of 16 rows; per-thread granule = 16B (8 halfs) at col gq*8
    int gid = wn * 32 + lane;
    int srow0 = wm * 64 + (gid >> 3);   // + it*16
    int gq = gid & 7;
    int barId = wm + 1;

    int rowi[8];
#pragma unroll
    for (int idx = 0; idx < 8; ++idx) {
        int mt = idx >> 1, half = idx & 1;
        rowi[idx] = n0 + RB + mt * 16 + g + half * 8;
    }

    for (int t = 0; t < T; ++t) {
        const float* Hin  = (t & 1) ? H1 : H0;
        float*       Hout = (t & 1) ? H0 : H1;
        int teff = d ? (T - 1 - t) : t;

        const __half* gxp[8];
#pragma unroll
        for (int idx = 0; idx < 8; ++idx) {
            int r = rowi[idx];
            if (r < N) {
                if (tok) {
                    int ti = r * T + teff;
                    int tv = is64 ? tok[2 * (size_t)ti] : tok[ti];
                    gxp[idx] = PV + ((size_t)d * VOCAB + tv) * G3;
                } else {
                    gxp[idx] = GX + ((size_t)d * N * T + (size_t)r * T + teff) * G3;
                }
            } else gxp[idx] = PV ? PV : GX;
        }

        float acc[3][4][4];
#pragma unroll
        for (int i = 0; i < 3; ++i)
#pragma unroll
            for (int j = 0; j < 4; ++j)
#pragma unroll
                for (int k = 0; k < 4; ++k) acc[i][j][k] = 0.f;

        if (t > 0) {   // step 0: Hin == 0 -> Gh == 0
            const float* Hb = Hin + (size_t)d * N * HD;
            uint4 pu[4];
#pragma unroll
            for (int it = 0; it < 4; ++it) {
                int rl = srow0 + it * 16;
                float4 a = make_float4(0.f,0.f,0.f,0.f), b = a;
                if (n0 + rl < N) {
                    const float* p = Hb + (size_t)(n0 + rl) * HD + gq * 8;
                    a = *(const float4*)p; b = *(const float4*)(p + 4);
                }
                pu[it] = make_uint4(f2h2u(a.x,a.y), f2h2u(a.z,a.w),
                                    f2h2u(b.x,b.y), f2h2u(b.z,b.w));
            }

            for (int k0i = 0; k0i < 4; ++k0i) {
                __half* buf = Hsm + (size_t)(k0i & 1) * 128 * HS3;
#pragma unroll
                for (int it = 0; it < 4; ++it)
                    *(uint4*)(buf + (size_t)(srow0 + it * 16) * HS3 + gq * 8) = pu[it];
                barhalf(barId);

                if (k0i < 3) {
                    int k0 = (k0i + 1) * 64;
#pragma unroll
                    for (int it = 0; it < 4; ++it) {
                        int rl = srow0 + it * 16;
                        float4 a = make_float4(0.f,0.f,0.f,0.f), b = a;
                        if (n0 + rl < N) {
                            const float* p = Hb + (size_t)(n0 + rl) * HD + k0 + gq * 8;
                            a = *(const float4*)p; b = *(const float4*)(p + 4);
                        }
                        pu[it] = make_uint4(f2h2u(a.x,a.y), f2h2u(a.z,a.w),
                                            f2h2u(b.x,b.y), f2h2u(b.z,b.w));
                    }
                }

                unsigned hbuf = (unsigned)((k0i & 1) * 128 * HS3 * 2);
                unsigned kwo  = (unsigned)(k0i * 128);   // 64 halfs in W rows
#pragma unroll
                for (int ks = 0; ks < 4; ++ks) {
                    unsigned kbo = (unsigned)(ks * 32);  // 16 halfs
                    unsigned a[4][4];
#pragma unroll
                    for (int mt = 0; mt < 4; ++mt)
                        ldsm4(a[mt][0], a[mt][1], a[mt][2], a[mt][3],
                              aAddr[mt] + hbuf + kbo);
                    unsigned b00, b01, b10, b11, b20, b21;
                    ldsm4(b00, b01, b10, b11, bAddr01 + kwo + kbo);
                    ldsm2(b20, b21, bAddr2 + kwo + kbo);
#pragma unroll
                    for (int mt = 0; mt < 4; ++mt) {
                        mma16(acc[0][mt], a[mt][0], a[mt][1], a[mt][2], a[mt][3], b00, b01);
                        mma16(acc[1][mt], a[mt][0], a[mt][1], a[mt][2], a[mt][3], b10, b11);
                        mma16(acc[2][mt], a[mt][0], a[mt][1], a[mt][2], a[mt][3], b20, b21);
                    }
                }
            }
        }

        // ---- gate math epilogue: 8 instances in 2 phases of 4 ----
#pragma unroll
        for (int phx = 0; phx < 2; ++phx) {
            float2 GR[4], GZ[4], GN[4], HH[4];
            bool val[4];
#pragma unroll
            for (int i = 0; i < 4; ++i) {
                int idx = phx * 4 + i;
                int r = rowi[idx];
                val[i] = (r < N);
                GR[i] = GZ[i] = GN[i] = HH[i] = make_float2(0.f, 0.f);
                if (val[i]) {
                    const __half* gxrow = gxp[idx];
                    GR[i] = __half22float2(*(const __half2*)(gxrow + cc));
                    GZ[i] = __half22float2(*(const __half2*)(gxrow + 256 + cc));
                    GN[i] = __half22float2(*(const __half2*)(gxrow + 512 + cc));
                    if (t > 0) HH[i] = *(const float2*)(Hin + (size_t)(d * N + r) * HD + cc);
                }
            }
#pragma unroll
            for (int i = 0; i < 4; ++i) {
                if (!val[i]) continue;
                int idx = phx * 4 + i;
                int mt = idx >> 1, half = idx & 1;
                float aR0 = acc[0][mt][half * 2 + 0], aR1 = acc[0][mt][half * 2 + 1];
                float aZ0 = acc[1][mt][half * 2 + 0], aZ1 = acc[1][mt][half * 2 + 1];
                float aN0 = acc[2][mt][half * 2 + 0], aN1 = acc[2][mt][half * 2 + 1];

                float r0 = fsigm(GR[i].x + aR0 + br2.x);
                float r1 = fsigm(GR[i].y + aR1 + br2.y);
                float z0 = fsigm(GZ[i].x + aZ0 + bz2.x);
                float z1 = fsigm(GZ[i].y + aZ1 + bz2.y);
                float n0v = ftanh(GN[i].x + r0 * (aN0 + bn2.x));
                float n1v = ftanh(GN[i].y + r1 * (aN1 + bn2.y));

                float2 o;
                o.x = n0v + z0 * (HH[i].x - n0v);
                o.y = n1v + z1 * (HH[i].y - n1v);
                *(float2*)(Hout + (size_t)(d * N + rowi[idx]) * HD + cc) = o;
            }
        }

        if (t + 1 < T) gbar(bid, gridDim.y, (unsigned)(t + 1));
    }
}

// ---------------- FC head: Linear(256->128) -> SELU -> Linear(128->1) on (X+X2) ----------------
__global__ void fc_head(const float* __restrict__ X, const float* __restrict__ X2,
                        const float* __restrict__ W1, const float* __restrict__ b1,
                        const float* __restrict__ W2, const float* __restrict__ b2,
                        float* __restrict__ out)
{
    int row = blockIdx.x;
    int h = threadIdx.x;  // 128 threads
    const float* x  = X  + (size_t)row * HD;
    const float* x2 = X2 + (size_t)row * HD;
    const float* w  = W1 + (size_t)h * HD;
    float s = 0.f;
#pragma unroll 8
    for (int k = 0; k < HD; k += 4) {
        float4 xv = *(const float4*)(x + k);
        float4 yv = *(const float4*)(x2 + k);
        float4 wv = *(const float4*)(w + k);
        s += (xv.x + yv.x) * wv.x + (xv.y + yv.y) * wv.y
           + (xv.z + yv.z) * wv.z + (xv.w + yv.w) * wv.w;
    }
    s += b1[h];
    const float SC = 1.0507009873554805f, AL = 1.6732632423543772f;
    float selu = SC * (s > 0.f ? s : AL * expm1f(s));
    float v = selu * W2[h];
    __shared__ float red[128];
    red[h] = v; __syncthreads();
    for (int st = 64; st > 0; st >>= 1) {
        if (h < st) red[h] += red[h + st];
        __syncthreads();
    }
    if (h == 0) out[row] = red[0] + b2[0];
}

// ---------------- launch ----------------
extern "C" void kernel_launch(void* const* d_in, const int* in_sizes, int n_in,
                              void* d_out, int out_size)
{
    const int*   tok   = (const int*)  d_in[0];
    const float* emb   = (const float*)d_in[1];
    const float* wWih  = (const float*)d_in[2];
    const float* wWhh  = (const float*)d_in[3];
    const float* wbih  = (const float*)d_in[4];
    const float* wbhh  = (const float*)d_in[5];
    const float* sWih  = (const float*)d_in[6];
    const float* sWhh  = (const float*)d_in[7];
    const float* sbih  = (const float*)d_in[8];
    const float* sbhh  = (const float*)d_in[9];
    const float* rWih  = (const float*)d_in[10];
    const float* rWhh  = (const float*)d_in[11];
    const float* rbih  = (const float*)d_in[12];
    const float* rbhh  = (const float*)d_in[13];
    const float* rfcW1 = (const float*)d_in[14];
    const float* rfcb1 = (const float*)d_in[15];
    const float* rfcW2 = (const float*)d_in[16];
    const float* rfcb2 = (const float*)d_in[17];
    const float* pfcW1 = (const float*)d_in[18];
    const float* pfcb1 = (const float*)d_in[19];
    const float* pfcW2 = (const float*)d_in[20];
    const float* pfcb2 = (const float*)d_in[21];
    float* out = (float*)d_out;

    static bool attr_set = false;
    if (!attr_set) {
        cudaFuncSetAttribute(gru_scan, cudaFuncAttributeMaxDynamicSharedMemorySize,
                             SCAN_SMEM_BYTES);
        cudaFuncSetAttribute(gemm_proj_mma, cudaFuncAttributeMaxDynamicSharedMemorySize,
                             GEMM_SMEM_BYTES);
        cudaFuncSetAttribute(gemm_proj_h, cudaFuncAttributeMaxDynamicSharedMemorySize,
                             GEMM_SMEM_BYTES);
        attr_set = true;
    }

    __half *pv, *gxs, *gxr, *eh, *wih16;
    float *hwB, *hsB, *hrB;
    cudaGetSymbolAddress((void**)&pv,    g_PV);
    cudaGetSymbolAddress((void**)&gxs,   g_GXs);
    cudaGetSymbolAddress((void**)&gxr,   g_GXr);
    cudaGetSymbolAddress((void**)&eh,    g_EH);
    cudaGetSymbolAddress((void**)&wih16, g_WIH);
    cudaGetSymbolAddress((void**)&hwB,   g_Hw);
    cudaGetSymbolAddress((void**)&hsB,   g_Hs);
    cudaGetSymbolAddress((void**)&hrB,   g_Hr);

    float* hw1 = hwB + (size_t)2 * NW * HD;
    float* hs1 = hsB + (size_t)2 * NS * HD;
    float* hr1 = hrB + (size_t)2 * NR * HD;

    kinit_bar<<<1, 1024>>>();

    // pre-convert emb and word Wih to fp16 (RN; identical rounding to in-loop cvt)
    cvt16<<<512, 256>>>(emb,  eh,    (size_t)VOCAB * HD);
    cvt16<<<128, 256>>>(wWih, wih16, (size_t)2 * G3 * HD);

    // project full vocabulary once per direction (pure fp16 inputs)
    gemm_proj_h<<<dim3((VOCAB + 127) / 128, G3 / 64, 2), 256, GEMM_SMEM_BYTES>>>(
        eh, VOCAB, wih16, wbih, pv);

    // word-level scan (T=32): grid (16, 8, 2), rowgroup barriers of 8 CTAs
    gru_scan<<<dim3(NW / 128, 8, 2), 256, SCAN_SMEM_BYTES>>>(
        hwB, hw1, wWhh, wbhh, nullptr, pv, tok, NW, TW, 0);
    float* hwF = (TW & 1) ? hw1 : hwB;

    // sentence-level: project (hf+hb fused) + scan (T=16)
    gemm_proj_mma<<<dim3((NW + 127) / 128, G3 / 64, 2), 256, GEMM_SMEM_BYTES>>>(
        hwF, hwF + (size_t)NW * HD, NW, sWih, sbih, gxs);
    gru_scan<<<dim3(1, 8, 2), 256, SCAN_SMEM_BYTES>>>(
        hsB, hs1, sWhh, sbhh, gxs, nullptr, nullptr, NS, TS, 32);
    float* hsF = (TS & 1) ? hs1 : hsB;

    // review-star head -> out[8..135]
    fc_head<<<NS, 128>>>(hsF, hsF + (size_t)NS * HD, rfcW1, rfcb1, rfcW2, rfcb2, out + NR);

    // review-level (business) biGRU: project (fused sum) + scan (T=16)
    gemm_proj_mma<<<dim3(1, G3 / 64, 2), 256, GEMM_SMEM_BYTES>>>(
        hsF, hsF + (size_t)NS * HD, NS, rWih, rbih, gxr);
    gru_scan<<<dim3(1, 8, 2), 256, SCAN_SMEM_BYTES>>>(
        hrB, hr1, rWhh, rbhh, gxr, nullptr, nullptr, NR, TR, 34);
    float* hrF = (TR & 1) ? hr1 : hrB;

    // business head -> out[0..7]
    fc_head<<<NR, 128>>>(hrF, hrF + (size_t)NR * HD, pfcW1, pfcb1, pfcW2, pfcb2, out);

    (void)in_sizes; (void)n_in; (void)out_size;
}

// round 15
// speedup vs baseline: 1.0194x; 1.0194x over previous
#include <cuda_runtime.h>
#include <cuda_fp16.h>
#include <cstdint>

// ---------------- problem constants ----------------
#define HD   256      // hidden / embedding dim
#define G3   768      // 3*H gate dim
#define VOCAB 30000
#define NW   2048     // word-level sequences (B*R*S)
#define TW   32       // word-level timesteps (W)
#define NS   128      // sentence-level sequences (B*R)
#define TS   16       // sentence-level timesteps (S)
#define NR   8        // review-level sequences (B)
#define TR   16       // review-level timesteps (R)

#define WH   264      // Wres row stride in halfs (528B -> conflict-free ldsm)
#define HS2  40       // tile row stride in halfs (80B; 16B-aligned rows)

// scan smem (halfs): Wres[96*WH] + Hsm[2][128][HS2]
#define SCAN_SMEM_BYTES ((96*WH + 2*128*HS2) * 2)
// gemm smem (halfs): As[2][128][HS2] + Bs[2][64][HS2]
#define GEMM_SMEM_BYTES ((2*128*HS2 + 2*64*HS2) * 2)

#define NBAR 36       // word 0..31, sentence 32..33, review 34..35
#define BPAD 32       // barrier slot padding (128B)

// ---------------- scratch (static device globals; no runtime alloc) ----------------
__device__ __half g_PV [(size_t)2*VOCAB*G3];       // projected vocab per dir (fp16)
__device__ __half g_GXs[(size_t)2*NS*TS*G3];       // sentence-level gx (fp16)
__device__ __half g_GXr[(size_t)2*NR*TR*G3];       // review-level gx (fp16)
__device__ __half g_EH [(size_t)VOCAB*HD];         // emb in fp16
__device__ __half g_WIH[(size_t)2*G3*HD];          // word Wih in fp16
__device__ float  g_Hw [2][(size_t)2*NW*HD];       // ping-pong hidden, word
__device__ float  g_Hs [2][(size_t)2*NS*HD];       // sentence
__device__ float  g_Hr [2][(size_t)2*NR*HD];       // review

// grid-barrier state: one padded slot per (scan, dir, rowgroup)
__device__ unsigned g_cnt[NBAR * BPAD];
__device__ volatile unsigned g_phase[NBAR * BPAD];

// ---------------- helpers ----------------
__device__ __forceinline__ float fsigm(float x) {
    float e = __expf(-x);
    return __fdividef(1.f, 1.f + e);
}
__device__ __forceinline__ float ftanh(float x) {
    float ax = fabsf(x);
    float e = __expf(-2.f * ax);
    float r = __fdividef(1.f - e, 1.f + e);
    return copysignf(r, x);
}

__device__ __forceinline__ unsigned f2h2u(float lo, float hi) {
    __half2 h = __floats2half2_rn(lo, hi);
    return *(unsigned*)&h;
}

__device__ __forceinline__ void mma16(float* d,
                                      unsigned a0, unsigned a1, unsigned a2, unsigned a3,
                                      unsigned b0, unsigned b1) {
    asm volatile(
        "mma.sync.aligned.m16n8k16.row.col.f32.f16.f16.f32 "
        "{%0,%1,%2,%3},{%4,%5,%6,%7},{%8,%9},{%0,%1,%2,%3};"
        : "+f"(d[0]), "+f"(d[1]), "+f"(d[2]), "+f"(d[3])
        : "r"(a0), "r"(a1), "r"(a2), "r"(a3), "r"(b0), "r"(b1));
}

__device__ __forceinline__ void ldsm4(unsigned& r0, unsigned& r1, unsigned& r2, unsigned& r3,
                                      unsigned addr) {
    asm volatile("ldmatrix.sync.aligned.m8n8.x4.shared.b16 {%0,%1,%2,%3}, [%4];"
                 : "=r"(r0), "=r"(r1), "=r"(r2), "=r"(r3) : "r"(addr));
}
__device__ __forceinline__ void ldsm2(unsigned& r0, unsigned& r1, unsigned addr) {
    asm volatile("ldmatrix.sync.aligned.m8n8.x2.shared.b16 {%0,%1}, [%2];"
                 : "=r"(r0), "=r"(r1) : "r"(addr));
}

// named barrier over 128 threads (4 warps), ids 1..2
__device__ __forceinline__ void barhalf(int id) {
    asm volatile("bar.sync %0, 128;" :: "r"(id) : "memory");
}

__global__ void kinit_bar() {
    for (int i = threadIdx.x; i < NBAR * BPAD; i += blockDim.x) {
        g_cnt[i] = 0; g_phase[i] = 0;
    }
}

// fp32 -> fp16 bulk convert
__global__ void cvt16(const float* __restrict__ src, __half* __restrict__ dst, size_t n) {
    size_t i = ((size_t)blockIdx.x * blockDim.x + threadIdx.x) * 4;
    size_t stride = (size_t)gridDim.x * blockDim.x * 4;
    for (; i < n; i += stride) {
        float4 v = *(const float4*)(src + i);
        *(uint2*)(dst + i) = make_uint2(f2h2u(v.x, v.y), f2h2u(v.z, v.w));
    }
}

// software grid barrier over an nCTA-member group (slot = id*BPAD)
__device__ __forceinline__ void gbar(int id, unsigned nCTA, unsigned target) {
    __syncthreads();
    if (threadIdx.x == 0) {
        __threadfence();
        unsigned* cnt = &g_cnt[id * BPAD];
        unsigned old = atomicAdd(cnt, 1u);
        if (old == nCTA - 1u) {
            *cnt = 0u;
            __threadfence();
            g_phase[id * BPAD] = target;
        } else {
            while (g_phase[id * BPAD] < target) __nanosleep(32);
        }
        __threadfence();
    }
    __syncthreads();
}

// ---------------- FP16-input GEMM: C[d][M,768] = A[M,256] @ W[d][768,256]^T + bias[d] ----------------
// A and W already fp16; 16B load granules. CTA 128x64, warps 4m x 2n, warp tile 32x32.
__global__ __launch_bounds__(256, 2)
void gemm_proj_h(const __half* __restrict__ A, int M,
                 const __half* __restrict__ W, const float* __restrict__ bias,
                 __half* __restrict__ C)
{
    extern __shared__ __half gsm[];
    __half* As = gsm;                   // [2][128][HS2]
    __half* Bs = gsm + 2 * 128 * HS2;   // [2][64][HS2]

    int d = blockIdx.z;
    const __half* Wd = W    + (size_t)d * G3 * HD;
    const float*  bd = bias + (size_t)d * G3;
    __half*       Cd = C    + (size_t)d * M * G3;

    int m0 = blockIdx.x * 128;
    int n0 = blockIdx.y * 64;

    int tid = threadIdx.x, lane = tid & 31, wid = tid >> 5;
    int wm = wid & 3, wn = wid >> 2;
    int RB = wm * 32, CB = wn * 32;
    int g = lane >> 2, c = lane & 3;

    int l7 = lane & 7, ts = lane >> 3;
    unsigned sAs = (unsigned)__cvta_generic_to_shared(As);
    unsigned sBs = (unsigned)__cvta_generic_to_shared(Bs);

    unsigned aAddr[2];
#pragma unroll
    for (int mt = 0; mt < 2; ++mt)
        aAddr[mt] = sAs + (unsigned)(((RB + mt * 16 + l7 + (ts & 1) * 8) * HS2
                                      + (ts >> 1) * 8) * 2);
    unsigned bAddr[2];
#pragma unroll
    for (int p = 0; p < 2; ++p)
        bAddr[p] = sBs + (unsigned)(((CB + (2 * p + (ts >> 1)) * 8 + l7) * HS2
                                     + (ts & 1) * 8) * 2);

    float acc[2][4][4];
#pragma unroll
    for (int i = 0; i < 2; ++i)
#pragma unroll
        for (int j = 0; j < 4; ++j)
#pragma unroll
            for (int k = 0; k < 4; ++k) acc[i][j][k] = 0.f;

    // 16B granules: A tile (128 rows x 32 halfs) = 512 granules -> 2 iters;
    // B tile (64 x 32) = 256 -> 1 iter. row = idx>>2, c16 = idx&3.
    int arow = tid >> 2, ac16 = tid & 3;

    uint4 pa[2], pw;
#pragma unroll
    for (int it = 0; it < 2; ++it) {
        int r = arow + it * 64;
        pa[it] = make_uint4(0u, 0u, 0u, 0u);
        if (m0 + r < M) pa[it] = *(const uint4*)(A + (size_t)(m0 + r) * HD + ac16 * 8);
    }
    pw = *(const uint4*)(Wd + (size_t)(n0 + arow) * HD + ac16 * 8);

#pragma unroll
    for (int it = 0; it < 2; ++it) {
        int r = arow + it * 64;
        *(uint4*)(As + (size_t)r * HS2 + ac16 * 8) = pa[it];
    }
    *(uint4*)(Bs + (size_t)arow * HS2 + ac16 * 8) = pw;
    __syncthreads();

    for (int k0i = 0; k0i < 8; ++k0i) {
        int cur = k0i & 1;
        if (k0i < 7) {
            int k0 = (k0i + 1) * 32;
#pragma unroll
            for (int it = 0; it < 2; ++it) {
                int r = arow + it * 64;
                pa[it] = make_uint4(0u, 0u, 0u, 0u);
                if (m0 + r < M) pa[it] = *(const uint4*)(A + (size_t)(m0 + r) * HD + k0 + ac16 * 8);
            }
            pw = *(const uint4*)(Wd + (size_t)(n0 + arow) * HD + k0 + ac16 * 8);
        }

        unsigned aBuf = (unsigned)(cur * 128 * HS2 * 2);
        unsigned bBuf = (unsigned)(cur * 64 * HS2 * 2);
#pragma unroll
        for (int ks = 0; ks < 2; ++ks) {
            unsigned kbo = (unsigned)(ks * 32);
            unsigned a[2][4];
#pragma unroll
            for (int mt = 0; mt < 2; ++mt)
                ldsm4(a[mt][0], a[mt][1], a[mt][2], a[mt][3], aAddr[mt] + aBuf + kbo);
            unsigned b[4][2];
#pragma unroll
            for (int p = 0; p < 2; ++p)
                ldsm4(b[2*p][0], b[2*p][1], b[2*p+1][0], b[2*p+1][1], bAddr[p] + bBuf + kbo);
#pragma unroll
            for (int nt = 0; nt < 4; ++nt)
#pragma unroll
                for (int mt = 0; mt < 2; ++mt)
                    mma16(acc[mt][nt], a[mt][0], a[mt][1], a[mt][2], a[mt][3],
                          b[nt][0], b[nt][1]);
        }

        if (k0i < 7) {
            __half* An = As + (size_t)(cur ^ 1) * 128 * HS2;
            __half* Bn = Bs + (size_t)(cur ^ 1) * 64 * HS2;
#pragma unroll
            for (int it = 0; it < 2; ++it) {
                int r = arow + it * 64;
                *(uint4*)(An + (size_t)r * HS2 + ac16 * 8) = pa[it];
            }
            *(uint4*)(Bn + (size_t)arow * HS2 + ac16 * 8) = pw;
        }
        __syncthreads();
    }

#pragma unroll
    for (int nt = 0; nt < 4; ++nt) {
        int col = n0 + CB + nt * 8 + 2 * c;
        float2 bb = *(const float2*)(bd + col);
#pragma unroll
        for (int mt = 0; mt < 2; ++mt) {
            int row0 = m0 + RB + mt * 16 + g;
            if (row0 < M)
                *(__half2*)(Cd + (size_t)row0 * G3 + col) =
                    __floats2half2_rn(acc[mt][nt][0] + bb.x, acc[mt][nt][1] + bb.y);
            int row1 = row0 + 8;
            if (row1 < M)
                *(__half2*)(Cd + (size_t)row1 * G3 + col) =
                    __floats2half2_rn(acc[mt][nt][2] + bb.x, acc[mt][nt][3] + bb.y);
        }
    }
}

// ---------------- FP32-input GEMM (fused A+A2): C fp16 ----------------
__global__ __launch_bounds__(256, 2)
void gemm_proj_mma(const float* __restrict__ A, const float* __restrict__ A2, int M,
                   const float* __restrict__ W, const float* __restrict__ bias,
                   __half* __restrict__ C)
{
    extern __shared__ __half gsm[];
    __half* As = gsm;                   // [2][128][HS2]
    __half* Bs = gsm + 2 * 128 * HS2;   // [2][64][HS2]

    int d = blockIdx.z;
    const float* Wd = W    + (size_t)d * G3 * HD;
    const float* bd = bias + (size_t)d * G3;
    __half*      Cd = C    + (size_t)d * M * G3;

    int m0 = blockIdx.x * 128;
    int n0 = blockIdx.y * 64;

    int tid = threadIdx.x, lane = tid & 31, wid = tid >> 5;
    int wm = wid & 3, wn = wid >> 2;
    int RB = wm * 32, CB = wn * 32;
    int g = lane >> 2, c = lane & 3;

    int l7 = lane & 7, ts = lane >> 3;
    unsigned sAs = (unsigned)__cvta_generic_to_shared(As);
    unsigned sBs = (unsigned)__cvta_generic_to_shared(Bs);

    unsigned aAddr[2];
#pragma unroll
    for (int mt = 0; mt < 2; ++mt)
        aAddr[mt] = sAs + (unsigned)(((RB + mt * 16 + l7 + (ts & 1) * 8) * HS2
                                      + (ts >> 1) * 8) * 2);
    unsigned bAddr[2];
#pragma unroll
    for (int p = 0; p < 2; ++p)
        bAddr[p] = sBs + (unsigned)(((CB + (2 * p + (ts >> 1)) * 8 + l7) * HS2
                                     + (ts & 1) * 8) * 2);

    float acc[2][4][4];
#pragma unroll
    for (int i = 0; i < 2; ++i)
#pragma unroll
        for (int j = 0; j < 4; ++j)
#pragma unroll
            for (int k = 0; k < 4; ++k) acc[i][j][k] = 0.f;

    int lr = tid >> 3, lq = tid & 7;

    float4 pa[4], pw[2];
#pragma unroll
    for (int it = 0; it < 4; ++it) {
        int r = lr + it * 32;
        pa[it] = make_float4(0.f, 0.f, 0.f, 0.f);
        if (m0 + r < M) {
            size_t off = (size_t)(m0 + r) * HD + lq * 4;
            pa[it] = *(const float4*)(A + off);
            if (A2) {
                float4 b = *(const float4*)(A2 + off);
                pa[it].x += b.x; pa[it].y += b.y; pa[it].z += b.z; pa[it].w += b.w;
            }
        }
    }
#pragma unroll
    for (int it = 0; it < 2; ++it) {
        int r = lr + it * 32;
        pw[it] = *(const float4*)(Wd + (size_t)(n0 + r) * HD + lq * 4);
    }
#pragma unroll
    for (int it = 0; it < 4; ++it) {
        int r = lr + it * 32;
        *(uint2*)(As + (size_t)r * HS2 + lq * 4) =
            make_uint2(f2h2u(pa[it].x, pa[it].y), f2h2u(pa[it].z, pa[it].w));
    }
#pragma unroll
    for (int it = 0; it < 2; ++it) {
        int r = lr + it * 32;
        *(uint2*)(Bs + (size_t)r * HS2 + lq * 4) =
            make_uint2(f2h2u(pw[it].x, pw[it].y), f2h2u(pw[it].z, pw[it].w));
    }
    __syncthreads();

    for (int k0i = 0; k0i < 8; ++k0i) {
        int cur = k0i & 1;
        if (k0i < 7) {
            int k0 = (k0i + 1) * 32;
#pragma unroll
            for (int it = 0; it < 4; ++it) {
                int r = lr + it * 32;
                pa[it] = make_float4(0.f, 0.f, 0.f, 0.f);
                if (m0 + r < M) {
                    size_t off = (size_t)(m0 + r) * HD + k0 + lq * 4;
                    pa[it] = *(const float4*)(A + off);
                    if (A2) {
                        float4 b = *(const float4*)(A2 + off);
                        pa[it].x += b.x; pa[it].y += b.y; pa[it].z += b.z; pa[it].w += b.w;
                    }
                }
            }
#pragma unroll
            for (int it = 0; it < 2; ++it) {
                int r = lr + it * 32;
                pw[it] = *(const float4*)(Wd + (size_t)(n0 + r) * HD + k0 + lq * 4);
            }
        }

        unsigned aBuf = (unsigned)(cur * 128 * HS2 * 2);
        unsigned bBuf = (unsigned)(cur * 64 * HS2 * 2);
#pragma unroll
        for (int ks = 0; ks < 2; ++ks) {
            unsigned kbo = (unsigned)(ks * 32);
            unsigned a[2][4];
#pragma unroll
            for (int mt = 0; mt < 2; ++mt)
                ldsm4(a[mt][0], a[mt][1], a[mt][2], a[mt][3], aAddr[mt] + aBuf + kbo);
            unsigned b[4][2];
#pragma unroll
            for (int p = 0; p < 2; ++p)
                ldsm4(b[2*p][0], b[2*p][1], b[2*p+1][0], b[2*p+1][1], bAddr[p] + bBuf + kbo);
#pragma unroll
            for (int nt = 0; nt < 4; ++nt)
#pragma unroll
                for (int mt = 0; mt < 2; ++mt)
                    mma16(acc[mt][nt], a[mt][0], a[mt][1], a[mt][2], a[mt][3],
                          b[nt][0], b[nt][1]);
        }

        if (k0i < 7) {
            __half* An = As + (size_t)(cur ^ 1) * 128 * HS2;
            __half* Bn = Bs + (size_t)(cur ^ 1) * 64 * HS2;
#pragma unroll
            for (int it = 0; it < 4; ++it) {
                int r = lr + it * 32;
                *(uint2*)(An + (size_t)r * HS2 + lq * 4) =
                    make_uint2(f2h2u(pa[it].x, pa[it].y), f2h2u(pa[it].z, pa[it].w));
            }
#pragma unroll
            for (int it = 0; it < 2; ++it) {
                int r = lr + it * 32;
                *(uint2*)(Bn + (size_t)r * HS2 + lq * 4) =
                    make_uint2(f2h2u(pw[it].x, pw[it].y), f2h2u(pw[it].z, pw[it].w));
            }
        }
        __syncthreads();
    }

#pragma unroll
    for (int nt = 0; nt < 4; ++nt) {
        int col = n0 + CB + nt * 8 + 2 * c;
        float2 bb = *(const float2*)(bd + col);
#pragma unroll
        for (int mt = 0; mt < 2; ++mt) {
            int row0 = m0 + RB + mt * 16 + g;
            if (row0 < M)
                *(__half2*)(Cd + (size_t)row0 * G3 + col) =
                    __floats2half2_rn(acc[mt][nt][0] + bb.x, acc[mt][nt][1] + bb.y);
            int row1 = row0 + 8;
            if (row1 < M)
                *(__half2*)(Cd + (size_t)row1 * G3 + col) =
                    __floats2half2_rn(acc[mt][nt][2] + bb.x, acc[mt][nt][3] + bb.y);
        }
    }
}

// ---------------- persistent fused GRU scan (fp16 MMA, 128x32 tile, 32-k chunks) ----------------
// Exact R13 structure: W resident fp16 (96 rows); H staged fp16 double-buffered,
// one 4-warp named barrier per 32-k chunk (8/step).
__global__ __launch_bounds__(256, 2)
void gru_scan(float* __restrict__ H0, float* __restrict__ H1,
              const float* __restrict__ Whh,    // [2][768][256]
              const float* __restrict__ bhh,    // [2][768]
              const __half* __restrict__ GX,    // [2][N*T][768] or nullptr
              const __half* __restrict__ PV,    // [2][VOCAB][768] or nullptr
              const int*   __restrict__ tok,    // tokens or nullptr
              int N, int T, int barBase)
{
    extern __shared__ __half smemh[];
    __half* Wres = smemh;                        // [96][WH] rows: gt*32 + j
    __half* Hsm  = smemh + 96 * WH;              // [2][128][HS2]

    int d  = blockIdx.z;
    int n0 = blockIdx.x * 128;
    int j0 = blockIdx.y * 32;
    int bid = barBase + d * gridDim.x + blockIdx.x;

    const float* Wd = Whh + (size_t)d * G3 * HD;

    int tid = threadIdx.x, lane = tid & 31, wid = tid >> 5;
    int wm = wid & 1, wn = wid >> 1;
    int RB = wm * 64, CB = wn * 8;
    int g = lane >> 2, c = lane & 3;

    // ---- load resident W slice (fp16 RN once): 96 rows x 256 cols ----
    for (int idx = tid; idx < 96 * 64; idx += 256) {
        int row = idx >> 6;
        int c4  = idx & 63;
        int gt = row >> 5, j = row & 31;
        float4 v = *(const float4*)(Wd + (size_t)(gt * 256 + j0 + j) * HD + c4 * 4);
        *(uint2*)(Wres + (size_t)row * WH + c4 * 4) =
            make_uint2(f2h2u(v.x, v.y), f2h2u(v.z, v.w));
    }
    __syncthreads();

    int l7 = lane & 7, ts = lane >> 3;
    unsigned sH = (unsigned)__cvta_generic_to_shared(Hsm);
    unsigned sW = (unsigned)__cvta_generic_to_shared(Wres);

    unsigned aAddr[4];
#pragma unroll
    for (int mt = 0; mt < 4; ++mt)
        aAddr[mt] = sH + (unsigned)(((RB + mt * 16 + l7 + (ts & 1) * 8) * HS2
                                     + (ts >> 1) * 8) * 2);
    unsigned bAddr01 = sW + (unsigned)((((ts >> 1) * 32 + CB + l7) * WH + (ts & 1) * 8) * 2);
    unsigned bAddr2  = sW + (unsigned)(((64 + CB + l7) * WH + (ts & 1) * 8) * 2);

    bool is64 = false;
    if (tok) is64 = (tok[1] == 0) & (tok[3] == 0) & (tok[5] == 0) & (tok[7] == 0);

    int cc = j0 + CB + 2 * c;
    float2 br2 = *(const float2*)(bhh + (size_t)d * G3 + cc);
    float2 bz2 = *(const float2*)(bhh + (size_t)d * G3 + 256 + cc);
    float2 bn2 = *(const float2*)(bhh + (size_t)d * G3 + 512 + cc);

    // staging: wm-group (128 threads) stages rows [wm*64, +64), 4 iters of 16 rows
    int gid = wn * 32 + lane;
    int srow0 = wm * 64 + (gid >> 3);   // + it*16
    int sq = gid & 7;
    int barId = wm + 1;

    int rowi[8];
#pragma unroll
    for (int idx = 0; idx < 8; ++idx) {
        int mt = idx >> 1, half = idx & 1;
        rowi[idx] = n0 + RB + mt * 16 + g + half * 8;
    }

    for (int t = 0; t < T; ++t) {
        const float* Hin  = (t & 1) ? H1 : H0;
        float*       Hout = (t & 1) ? H0 : H1;
        int teff = d ? (T - 1 - t) : t;

        const __half* gxp[8];
#pragma unroll
        for (int idx = 0; idx < 8; ++idx) {
            int r = rowi[idx];
            if (r < N) {
                if (tok) {
                    int ti = r * T + teff;
                    int tv = is64 ? tok[2 * (size_t)ti] : tok[ti];
                    gxp[idx] = PV + ((size_t)d * VOCAB + tv) * G3;
                } else {
                    gxp[idx] = GX + ((size_t)d * N * T + (size_t)r * T + teff) * G3;
                }
            } else gxp[idx] = PV ? PV : GX;
        }

        float acc[3][4][4];
#pragma unroll
        for (int i = 0; i < 3; ++i)
#pragma unroll
            for (int j = 0; j < 4; ++j)
#pragma unroll
                for (int k = 0; k < 4; ++k) acc[i][j][k] = 0.f;

        if (t > 0) {   // step 0: Hin == 0 -> Gh == 0
            float4 ph[4];
#pragma unroll
            for (int it = 0; it < 4; ++it) {
                int rl = srow0 + it * 16;
                ph[it] = make_float4(0.f, 0.f, 0.f, 0.f);
                if (n0 + rl < N)
                    ph[it] = *(const float4*)(Hin + (size_t)(d * N + n0 + rl) * HD + sq * 4);
            }

            for (int k0i = 0; k0i < 8; ++k0i) {
                __half* buf = Hsm + (size_t)(k0i & 1) * 128 * HS2;
#pragma unroll
                for (int it = 0; it < 4; ++it)
                    *(uint2*)(buf + (size_t)(srow0 + it * 16) * HS2 + sq * 4) =
                        make_uint2(f2h2u(ph[it].x, ph[it].y), f2h2u(ph[it].z, ph[it].w));
                barhalf(barId);

                if (k0i < 7) {
                    int k0 = (k0i + 1) * 32;
#pragma unroll
                    for (int it = 0; it < 4; ++it) {
                        int rl = srow0 + it * 16;
                        ph[it] = make_float4(0.f, 0.f, 0.f, 0.f);
                        if (n0 + rl < N)
                            ph[it] = *(const float4*)(Hin + (size_t)(d * N + n0 + rl) * HD + k0 + sq * 4);
                    }
                }

                unsigned hbuf = (unsigned)((k0i & 1) * 128 * HS2 * 2);
                unsigned kwo  = (unsigned)(k0i * 64);   // 32 halfs per chunk in W
#pragma unroll
                for (int ks = 0; ks < 2; ++ks) {
                    unsigned kbo = (unsigned)(ks * 32); // 16 halfs
                    unsigned a[4][4];
#pragma unroll
                    for (int mt = 0; mt < 4; ++mt)
                        ldsm4(a[mt][0], a[mt][1], a[mt][2], a[mt][3],
                              aAddr[mt] + hbuf + kbo);
                    unsigned b00, b01, b10, b11, b20, b21;
                    ldsm4(b00, b01, b10, b11, bAddr01 + kwo + kbo);
                    ldsm2(b20, b21, bAddr2 + kwo + kbo);
#pragma unroll
                    for (int mt = 0; mt < 4; ++mt) {
                        mma16(acc[0][mt], a[mt][0], a[mt][1], a[mt][2], a[mt][3], b00, b01);
                        mma16(acc[1][mt], a[mt][0], a[mt][1], a[mt][2], a[mt][3], b10, b11);
                        mma16(acc[2][mt], a[mt][0], a[mt][1], a[mt][2], a[mt][3], b20, b21);
                    }
                }
            }
        }

        // ---- gate math epilogue: 8 instances in 2 phases of 4 ----
#pragma unroll
        for (int phx = 0; phx < 2; ++phx) {
            float2 GR[4], GZ[4], GN[4], HH[4];
            bool val[4];
#pragma unroll
            for (int i = 0; i < 4; ++i) {
                int idx = phx * 4 + i;
                int r = rowi[idx];
                val[i] = (r < N);
                GR[i] = GZ[i] = GN[i] = HH[i] = make_float2(0.f, 0.f);
                if (val[i]) {
                    const __half* gxrow = gxp[idx];
                    GR[i] = __half22float2(*(const __half2*)(gxrow + cc));
                    GZ[i] = __half22float2(*(const __half2*)(gxrow + 256 + cc));
                    GN[i] = __half22float2(*(const __half2*)(gxrow + 512 + cc));
                    if (t > 0) HH[i] = *(const float2*)(Hin + (size_t)(d * N + r) * HD + cc);
                }
            }
#pragma unroll
            for (int i = 0; i < 4; ++i) {
                if (!val[i]) continue;
                int idx = phx * 4 + i;
                int mt = idx >> 1, half = idx & 1;
                float aR0 = acc[0][mt][half * 2 + 0], aR1 = acc[0][mt][half * 2 + 1];
                float aZ0 = acc[1][mt][half * 2 + 0], aZ1 = acc[1][mt][half * 2 + 1];
                float aN0 = acc[2][mt][half * 2 + 0], aN1 = acc[2][mt][half * 2 + 1];

                float r0 = fsigm(GR[i].x + aR0 + br2.x);
                float r1 = fsigm(GR[i].y + aR1 + br2.y);
                float z0 = fsigm(GZ[i].x + aZ0 + bz2.x);
                float z1 = fsigm(GZ[i].y + aZ1 + bz2.y);
                float n0v = ftanh(GN[i].x + r0 * (aN0 + bn2.x));
                float n1v = ftanh(GN[i].y + r1 * (aN1 + bn2.y));

                float2 o;
                o.x = n0v + z0 * (HH[i].x - n0v);
                o.y = n1v + z1 * (HH[i].y - n1v);
                *(float2*)(Hout + (size_t)(d * N + rowi[idx]) * HD + cc) = o;
            }
        }

        if (t + 1 < T) gbar(bid, gridDim.y, (unsigned)(t + 1));
    }
}

// ---------------- FC head: Linear(256->128) -> SELU -> Linear(128->1) on (X+X2) ----------------
__global__ void fc_head(const float* __restrict__ X, const float* __restrict__ X2,
                        const float* __restrict__ W1, const float* __restrict__ b1,
                        const float* __restrict__ W2, const float* __restrict__ b2,
                        float* __restrict__ out)
{
    int row = blockIdx.x;
    int h = threadIdx.x;  // 128 threads
    const float* x  = X  + (size_t)row * HD;
    const float* x2 = X2 + (size_t)row * HD;
    const float* w  = W1 + (size_t)h * HD;
    float s = 0.f;
#pragma unroll 8
    for (int k = 0; k < HD; k += 4) {
        float4 xv = *(const float4*)(x + k);
        float4 yv = *(const float4*)(x2 + k);
        float4 wv = *(const float4*)(w + k);
        s += (xv.x + yv.x) * wv.x + (xv.y + yv.y) * wv.y
           + (xv.z + yv.z) * wv.z + (xv.w + yv.w) * wv.w;
    }
    s += b1[h];
    const float SC = 1.0507009873554805f, AL = 1.6732632423543772f;
    float selu = SC * (s > 0.f ? s : AL * expm1f(s));
    float v = selu * W2[h];
    __shared__ float red[128];
    red[h] = v; __syncthreads();
    for (int st = 64; st > 0; st >>= 1) {
        if (h < st) red[h] += red[h + st];
        __syncthreads();
    }
    if (h == 0) out[row] = red[0] + b2[0];
}

// ---------------- launch ----------------
extern "C" void kernel_launch(void* const* d_in, const int* in_sizes, int n_in,
                              void* d_out, int out_size)
{
    const int*   tok   = (const int*)  d_in[0];
    const float* emb   = (const float*)d_in[1];
    const float* wWih  = (const float*)d_in[2];
    const float* wWhh  = (const float*)d_in[3];
    const float* wbih  = (const float*)d_in[4];
    const float* wbhh  = (const float*)d_in[5];
    const float* sWih  = (const float*)d_in[6];
    const float* sWhh  = (const float*)d_in[7];
    const float* sbih  = (const float*)d_in[8];
    const float* sbhh  = (const float*)d_in[9];
    const float* rWih  = (const float*)d_in[10];
    const float* rWhh  = (const float*)d_in[11];
    const float* rbih  = (const float*)d_in[12];
    const float* rbhh  = (const float*)d_in[13];
    const float* rfcW1 = (const float*)d_in[14];
    const float* rfcb1 = (const float*)d_in[15];
    const float* rfcW2 = (const float*)d_in[16];
    const float* rfcb2 = (const float*)d_in[17];
    const float* pfcW1 = (const float*)d_in[18];
    const float* pfcb1 = (const float*)d_in[19];
    const float* pfcW2 = (const float*)d_in[20];
    const float* pfcb2 = (const float*)d_in[21];
    float* out = (float*)d_out;

    static bool attr_set = false;
    if (!attr_set) {
        cudaFuncSetAttribute(gru_scan, cudaFuncAttributeMaxDynamicSharedMemorySize,
                             SCAN_SMEM_BYTES);
        cudaFuncSetAttribute(gemm_proj_mma, cudaFuncAttributeMaxDynamicSharedMemorySize,
                             GEMM_SMEM_BYTES);
        cudaFuncSetAttribute(gemm_proj_h, cudaFuncAttributeMaxDynamicSharedMemorySize,
                             GEMM_SMEM_BYTES);
        attr_set = true;
    }

    __half *pv, *gxs, *gxr, *eh, *wih16;
    float *hwB, *hsB, *hrB;
    cudaGetSymbolAddress((void**)&pv,    g_PV);
    cudaGetSymbolAddress((void**)&gxs,   g_GXs);
    cudaGetSymbolAddress((void**)&gxr,   g_GXr);
    cudaGetSymbolAddress((void**)&eh,    g_EH);
    cudaGetSymbolAddress((void**)&wih16, g_WIH);
    cudaGetSymbolAddress((void**)&hwB,   g_Hw);
    cudaGetSymbolAddress((void**)&hsB,   g_Hs);
    cudaGetSymbolAddress((void**)&hrB,   g_Hr);

    float* hw1 = hwB + (size_t)2 * NW * HD;
    float* hs1 = hsB + (size_t)2 * NS * HD;
    float* hr1 = hrB + (size_t)2 * NR * HD;

    kinit_bar<<<1, 1024>>>();

    // pre-convert emb and word Wih to fp16 (RN; identical rounding to in-loop cvt)
    cvt16<<<512, 256>>>(emb,  eh,    (size_t)VOCAB * HD);
    cvt16<<<64,  256>>>(wWih, wih16, (size_t)2 * G3 * HD);

    // project full vocabulary once per direction (pure fp16 inputs, 16B granules)
    gemm_proj_h<<<dim3((VOCAB + 127) / 128, G3 / 64, 2), 256, GEMM_SMEM_BYTES>>>(
        eh, VOCAB, wih16, wbih, pv);

    // word-level scan (T=32): grid (16, 8, 2), rowgroup barriers of 8 CTAs
    gru_scan<<<dim3(NW / 128, 8, 2), 256, SCAN_SMEM_BYTES>>>(
        hwB, hw1, wWhh, wbhh, nullptr, pv, tok, NW, TW, 0);
    float* hwF = (TW & 1) ? hw1 : hwB;

    // sentence-level: project (hf+hb fused) + scan (T=16)
    gemm_proj_mma<<<dim3((NW + 127) / 128, G3 / 64, 2), 256, GEMM_SMEM_BYTES>>>(
        hwF, hwF + (size_t)NW * HD, NW, sWih, sbih, gxs);
    gru_scan<<<dim3(1, 8, 2), 256, SCAN_SMEM_BYTES>>>(
        hsB, hs1, sWhh, sbhh, gxs, nullptr, nullptr, NS, TS, 32);
    float* hsF = (TS & 1) ? hs1 : hsB;

    // review-star head -> out[8..135]
    fc_head<<<NS, 128>>>(hsF, hsF + (size_t)NS * HD, rfcW1, rfcb1, rfcW2, rfcb2, out + NR);

    // review-level (business) biGRU: project (fused sum) + scan (T=16)
    gemm_proj_mma<<<dim3(1, G3 / 64, 2), 256, GEMM_SMEM_BYTES>>>(
        hsF, hsF + (size_t)NS * HD, NS, rWih, rbih, gxr);
    gru_scan<<<dim3(1, 8, 2), 256, SCAN_SMEM_BYTES>>>(
        hrB, hr1, rWhh, rbhh, gxr, nullptr, nullptr, NR, TR, 34);
    float* hrF = (TR & 1) ? hr1 : hrB;

    // business head -> out[0..7]
    fc_head<<<NR, 128>>>(hrF, hrF + (size_t)NR * HD, pfcW1, pfcb1, pfcW2, pfcb2, out);

    (void)in_sizes; (void)n_in; (void)out_size;
}

// round 16
// speedup vs baseline: 1.0241x; 1.0045x over previous
#include <cuda_runtime.h>
#include <cuda_fp16.h>
#include <cstdint>

// ---------------- problem constants ----------------
#define HD   256      // hidden / embedding dim
#define G3   768      // 3*H gate dim
#define VOCAB 30000
#define NW   2048     // word-level sequences (B*R*S)
#define TW   32       // word-level timesteps (W)
#define NS   128      // sentence-level sequences (B*R)
#define TS   16       // sentence-level timesteps (S)
#define NR   8        // review-level sequences (B)
#define TR   16       // review-level timesteps (R)

#define WH   264      // Wres row stride in halfs (528B -> conflict-free ldsm)
#define HS2  40       // tile row stride in halfs (80B; 16B-aligned rows)

// scan smem (halfs): Wres[96*WH] + Hsm[2][128][HS2]
#define SCAN_SMEM_BYTES ((96*WH + 2*128*HS2) * 2)
// gemm smem (halfs): As[2][128][HS2] + Bs[2][64][HS2]
#define GEMM_SMEM_BYTES ((2*128*HS2 + 2*64*HS2) * 2)

#define NBAR 36       // word 0..31, sentence 32..33, review 34..35
#define BPAD 32       // barrier slot padding (128B)

// ---------------- scratch (static device globals; no runtime alloc) ----------------
__device__ __half g_PV [(size_t)2*VOCAB*G3];       // projected vocab per dir (fp16)
__device__ __half g_GXs[(size_t)2*NS*TS*G3];       // sentence-level gx (fp16)
__device__ __half g_GXr[(size_t)2*NR*TR*G3];       // review-level gx (fp16)
__device__ __half g_EH [(size_t)VOCAB*HD];         // emb in fp16
__device__ __half g_WIH[(size_t)2*G3*HD];          // word Wih in fp16
__device__ float  g_Hw [2][(size_t)2*NW*HD];       // ping-pong hidden fp32, word
__device__ float  g_Hs [2][(size_t)2*NS*HD];       // sentence
__device__ float  g_Hr [2][(size_t)2*NR*HD];       // review
__device__ __half g_HwH[2][(size_t)2*NW*HD];       // fp16 mirror of H (MMA operand)
__device__ __half g_HsH[2][(size_t)2*NS*HD];
__device__ __half g_HrH[2][(size_t)2*NR*HD];

// grid-barrier state: one padded slot per (scan, dir, rowgroup)
__device__ unsigned g_cnt[NBAR * BPAD];
__device__ volatile unsigned g_phase[NBAR * BPAD];

// ---------------- helpers ----------------
__device__ __forceinline__ float fsigm(float x) {
    float e = __expf(-x);
    return __fdividef(1.f, 1.f + e);
}
__device__ __forceinline__ float ftanh(float x) {
    float ax = fabsf(x);
    float e = __expf(-2.f * ax);
    float r = __fdividef(1.f - e, 1.f + e);
    return copysignf(r, x);
}

__device__ __forceinline__ unsigned f2h2u(float lo, float hi) {
    __half2 h = __floats2half2_rn(lo, hi);
    return *(unsigned*)&h;
}

__device__ __forceinline__ void mma16(float* d,
                                      unsigned a0, unsigned a1, unsigned a2, unsigned a3,
                                      unsigned b0, unsigned b1) {
    asm volatile(
        "mma.sync.aligned.m16n8k16.row.col.f32.f16.f16.f32 "
        "{%0,%1,%2,%3},{%4,%5,%6,%7},{%8,%9},{%0,%1,%2,%3};"
        : "+f"(d[0]), "+f"(d[1]), "+f"(d[2]), "+f"(d[3])
        : "r"(a0), "r"(a1), "r"(a2), "r"(a3), "r"(b0), "r"(b1));
}

__device__ __forceinline__ void ldsm4(unsigned& r0, unsigned& r1, unsigned& r2, unsigned& r3,
                                      unsigned addr) {
    asm volatile("ldmatrix.sync.aligned.m8n8.x4.shared.b16 {%0,%1,%2,%3}, [%4];"
                 : "=r"(r0), "=r"(r1), "=r"(r2), "=r"(r3) : "r"(addr));
}
__device__ __forceinline__ void ldsm2(unsigned& r0, unsigned& r1, unsigned addr) {
    asm volatile("ldmatrix.sync.aligned.m8n8.x2.shared.b16 {%0,%1}, [%2];"
                 : "=r"(r0), "=r"(r1) : "r"(addr));
}

// named barrier over 128 threads (4 warps), ids 1..2
__device__ __forceinline__ void barhalf(int id) {
    asm volatile("bar.sync %0, 128;" :: "r"(id) : "memory");
}

__global__ void kinit_bar() {
    for (int i = threadIdx.x; i < NBAR * BPAD; i += blockDim.x) {
        g_cnt[i] = 0; g_phase[i] = 0;
    }
}

// fp32 -> fp16 bulk convert
__global__ void cvt16(const float* __restrict__ src, __half* __restrict__ dst, size_t n) {
    size_t i = ((size_t)blockIdx.x * blockDim.x + threadIdx.x) * 4;
    size_t stride = (size_t)gridDim.x * blockDim.x * 4;
    for (; i < n; i += stride) {
        float4 v = *(const float4*)(src + i);
        *(uint2*)(dst + i) = make_uint2(f2h2u(v.x, v.y), f2h2u(v.z, v.w));
    }
}

// software grid barrier over an nCTA-member group (slot = id*BPAD)
__device__ __forceinline__ void gbar(int id, unsigned nCTA, unsigned target) {
    __syncthreads();
    if (threadIdx.x == 0) {
        __threadfence();
        unsigned* cnt = &g_cnt[id * BPAD];
        unsigned old = atomicAdd(cnt, 1u);
        if (old == nCTA - 1u) {
            *cnt = 0u;
            __threadfence();
            g_phase[id * BPAD] = target;
        } else {
            while (g_phase[id * BPAD] < target) __nanosleep(32);
        }
        __threadfence();
    }
    __syncthreads();
}

// ---------------- FP16-input GEMM: C[d][M,768] = A[M,256] @ W[d][768,256]^T + bias[d] ----------------
__global__ __launch_bounds__(256, 2)
void gemm_proj_h(const __half* __restrict__ A, int M,
                 const __half* __restrict__ W, const float* __restrict__ bias,
                 __half* __restrict__ C)
{
    extern __shared__ __half gsm[];
    __half* As = gsm;                   // [2][128][HS2]
    __half* Bs = gsm + 2 * 128 * HS2;   // [2][64][HS2]

    int d = blockIdx.z;
    const __half* Wd = W    + (size_t)d * G3 * HD;
    const float*  bd = bias + (size_t)d * G3;
    __half*       Cd = C    + (size_t)d * M * G3;

    int m0 = blockIdx.x * 128;
    int n0 = blockIdx.y * 64;

    int tid = threadIdx.x, lane = tid & 31, wid = tid >> 5;
    int wm = wid & 3, wn = wid >> 2;
    int RB = wm * 32, CB = wn * 32;
    int g = lane >> 2, c = lane & 3;

    int l7 = lane & 7, ts = lane >> 3;
    unsigned sAs = (unsigned)__cvta_generic_to_shared(As);
    unsigned sBs = (unsigned)__cvta_generic_to_shared(Bs);

    unsigned aAddr[2];
#pragma unroll
    for (int mt = 0; mt < 2; ++mt)
        aAddr[mt] = sAs + (unsigned)(((RB + mt * 16 + l7 + (ts & 1) * 8) * HS2
                                      + (ts >> 1) * 8) * 2);
    unsigned bAddr[2];
#pragma unroll
    for (int p = 0; p < 2; ++p)
        bAddr[p] = sBs + (unsigned)(((CB + (2 * p + (ts >> 1)) * 8 + l7) * HS2
                                     + (ts & 1) * 8) * 2);

    float acc[2][4][4];
#pragma unroll
    for (int i = 0; i < 2; ++i)
#pragma unroll
        for (int j = 0; j < 4; ++j)
#pragma unroll
            for (int k = 0; k < 4; ++k) acc[i][j][k] = 0.f;

    int arow = tid >> 2, ac16 = tid & 3;

    uint4 pa[2], pw;
#pragma unroll
    for (int it = 0; it < 2; ++it) {
        int r = arow + it * 64;
        pa[it] = make_uint4(0u, 0u, 0u, 0u);
        if (m0 + r < M) pa[it] = *(const uint4*)(A + (size_t)(m0 + r) * HD + ac16 * 8);
    }
    pw = *(const uint4*)(Wd + (size_t)(n0 + arow) * HD + ac16 * 8);

#pragma unroll
    for (int it = 0; it < 2; ++it) {
        int r = arow + it * 64;
        *(uint4*)(As + (size_t)r * HS2 + ac16 * 8) = pa[it];
    }
    *(uint4*)(Bs + (size_t)arow * HS2 + ac16 * 8) = pw;
    __syncthreads();

    for (int k0i = 0; k0i < 8; ++k0i) {
        int cur = k0i & 1;
        if (k0i < 7) {
            int k0 = (k0i + 1) * 32;
#pragma unroll
            for (int it = 0; it < 2; ++it) {
                int r = arow + it * 64;
                pa[it] = make_uint4(0u, 0u, 0u, 0u);
                if (m0 + r < M) pa[it] = *(const uint4*)(A + (size_t)(m0 + r) * HD + k0 + ac16 * 8);
            }
            pw = *(const uint4*)(Wd + (size_t)(n0 + arow) * HD + k0 + ac16 * 8);
        }

        unsigned aBuf = (unsigned)(cur * 128 * HS2 * 2);
        unsigned bBuf = (unsigned)(cur * 64 * HS2 * 2);
#pragma unroll
        for (int ks = 0; ks < 2; ++ks) {
            unsigned kbo = (unsigned)(ks * 32);
            unsigned a[2][4];
#pragma unroll
            for (int mt = 0; mt < 2; ++mt)
                ldsm4(a[mt][0], a[mt][1], a[mt][2], a[mt][3], aAddr[mt] + aBuf + kbo);
            unsigned b[4][2];
#pragma unroll
            for (int p = 0; p < 2; ++p)
                ldsm4(b[2*p][0], b[2*p][1], b[2*p+1][0], b[2*p+1][1], bAddr[p] + bBuf + kbo);
#pragma unroll
            for (int nt = 0; nt < 4; ++nt)
#pragma unroll
                for (int mt = 0; mt < 2; ++mt)
                    mma16(acc[mt][nt], a[mt][0], a[mt][1], a[mt][2], a[mt][3],
                          b[nt][0], b[nt][1]);
        }

        if (k0i < 7) {
            __half* An = As + (size_t)(cur ^ 1) * 128 * HS2;
            __half* Bn = Bs + (size_t)(cur ^ 1) * 64 * HS2;
#pragma unroll
            for (int it = 0; it < 2; ++it) {
                int r = arow + it * 64;
                *(uint4*)(An + (size_t)r * HS2 + ac16 * 8) = pa[it];
            }
            *(uint4*)(Bn + (size_t)arow * HS2 + ac16 * 8) = pw;
        }
        __syncthreads();
    }

#pragma unroll
    for (int nt = 0; nt < 4; ++nt) {
        int col = n0 + CB + nt * 8 + 2 * c;
        float2 bb = *(const float2*)(bd + col);
#pragma unroll
        for (int mt = 0; mt < 2; ++mt) {
            int row0 = m0 + RB + mt * 16 + g;
            if (row0 < M)
                *(__half2*)(Cd + (size_t)row0 * G3 + col) =
                    __floats2half2_rn(acc[mt][nt][0] + bb.x, acc[mt][nt][1] + bb.y);
            int row1 = row0 + 8;
            if (row1 < M)
                *(__half2*)(Cd + (size_t)row1 * G3 + col) =
                    __floats2half2_rn(acc[mt][nt][2] + bb.x, acc[mt][nt][3] + bb.y);
        }
    }
}

// ---------------- FP32-input GEMM (fused A+A2): C fp16 ----------------
__global__ __launch_bounds__(256, 2)
void gemm_proj_mma(const float* __restrict__ A, const float* __restrict__ A2, int M,
                   const float* __restrict__ W, const float* __restrict__ bias,
                   __half* __restrict__ C)
{
    extern __shared__ __half gsm[];
    __half* As = gsm;                   // [2][128][HS2]
    __half* Bs = gsm + 2 * 128 * HS2;   // [2][64][HS2]

    int d = blockIdx.z;
    const float* Wd = W    + (size_t)d * G3 * HD;
    const float* bd = bias + (size_t)d * G3;
    __half*      Cd = C    + (size_t)d * M * G3;

    int m0 = blockIdx.x * 128;
    int n0 = blockIdx.y * 64;

    int tid = threadIdx.x, lane = tid & 31, wid = tid >> 5;
    int wm = wid & 3, wn = wid >> 2;
    int RB = wm * 32, CB = wn * 32;
    int g = lane >> 2, c = lane & 3;

    int l7 = lane & 7, ts = lane >> 3;
    unsigned sAs = (unsigned)__cvta_generic_to_shared(As);
    unsigned sBs = (unsigned)__cvta_generic_to_shared(Bs);

    unsigned aAddr[2];
#pragma unroll
    for (int mt = 0; mt < 2; ++mt)
        aAddr[mt] = sAs + (unsigned)(((RB + mt * 16 + l7 + (ts & 1) * 8) * HS2
                                      + (ts >> 1) * 8) * 2);
    unsigned bAddr[2];
#pragma unroll
    for (int p = 0; p < 2; ++p)
        bAddr[p] = sBs + (unsigned)(((CB + (2 * p + (ts >> 1)) * 8 + l7) * HS2
                                     + (ts & 1) * 8) * 2);

    float acc[2][4][4];
#pragma unroll
    for (int i = 0; i < 2; ++i)
#pragma unroll
        for (int j = 0; j < 4; ++j)
#pragma unroll
            for (int k = 0; k < 4; ++k) acc[i][j][k] = 0.f;

    int lr = tid >> 3, lq = tid & 7;

    float4 pa[4], pw[2];
#pragma unroll
    for (int it = 0; it < 4; ++it) {
        int r = lr + it * 32;
        pa[it] = make_float4(0.f, 0.f, 0.f, 0.f);
        if (m0 + r < M) {
            size_t off = (size_t)(m0 + r) * HD + lq * 4;
            pa[it] = *(const float4*)(A + off);
            if (A2) {
                float4 b = *(const float4*)(A2 + off);
                pa[it].x += b.x; pa[it].y += b.y; pa[it].z += b.z; pa[it].w += b.w;
            }
        }
    }
#pragma unroll
    for (int it = 0; it < 2; ++it) {
        int r = lr + it * 32;
        pw[it] = *(const float4*)(Wd + (size_t)(n0 + r) * HD + lq * 4);
    }
#pragma unroll
    for (int it = 0; it < 4; ++it) {
        int r = lr + it * 32;
        *(uint2*)(As + (size_t)r * HS2 + lq * 4) =
            make_uint2(f2h2u(pa[it].x, pa[it].y), f2h2u(pa[it].z, pa[it].w));
    }
#pragma unroll
    for (int it = 0; it < 2; ++it) {
        int r = lr + it * 32;
        *(uint2*)(Bs + (size_t)r * HS2 + lq * 4) =
            make_uint2(f2h2u(pw[it].x, pw[it].y), f2h2u(pw[it].z, pw[it].w));
    }
    __syncthreads();

    for (int k0i = 0; k0i < 8; ++k0i) {
        int cur = k0i & 1;
        if (k0i < 7) {
            int k0 = (k0i + 1) * 32;
#pragma unroll
            for (int it = 0; it < 4; ++it) {
                int r = lr + it * 32;
                pa[it] = make_float4(0.f, 0.f, 0.f, 0.f);
                if (m0 + r < M) {
                    size_t off = (size_t)(m0 + r) * HD + k0 + lq * 4;
                    pa[it] = *(const float4*)(A + off);
                    if (A2) {
                        float4 b = *(const float4*)(A2 + off);
                        pa[it].x += b.x; pa[it].y += b.y; pa[it].z += b.z; pa[it].w += b.w;
                    }
                }
            }
#pragma unroll
            for (int it = 0; it < 2; ++it) {
                int r = lr + it * 32;
                pw[it] = *(const float4*)(Wd + (size_t)(n0 + r) * HD + k0 + lq * 4);
            }
        }

        unsigned aBuf = (unsigned)(cur * 128 * HS2 * 2);
        unsigned bBuf = (unsigned)(cur * 64 * HS2 * 2);
#pragma unroll
        for (int ks = 0; ks < 2; ++ks) {
            unsigned kbo = (unsigned)(ks * 32);
            unsigned a[2][4];
#pragma unroll
            for (int mt = 0; mt < 2; ++mt)
                ldsm4(a[mt][0], a[mt][1], a[mt][2], a[mt][3], aAddr[mt] + aBuf + kbo);
            unsigned b[4][2];
#pragma unroll
            for (int p = 0; p < 2; ++p)
                ldsm4(b[2*p][0], b[2*p][1], b[2*p+1][0], b[2*p+1][1], bAddr[p] + bBuf + kbo);
#pragma unroll
            for (int nt = 0; nt < 4; ++nt)
#pragma unroll
                for (int mt = 0; mt < 2; ++mt)
                    mma16(acc[mt][nt], a[mt][0], a[mt][1], a[mt][2], a[mt][3],
                          b[nt][0], b[nt][1]);
        }

        if (k0i < 7) {
            __half* An = As + (size_t)(cur ^ 1) * 128 * HS2;
            __half* Bn = Bs + (size_t)(cur ^ 1) * 64 * HS2;
#pragma unroll
            for (int it = 0; it < 4; ++it) {
                int r = lr + it * 32;
                *(uint2*)(An + (size_t)r * HS2 + lq * 4) =
                    make_uint2(f2h2u(pa[it].x, pa[it].y), f2h2u(pa[it].z, pa[it].w));
            }
#pragma unroll
            for (int it = 0; it < 2; ++it) {
                int r = lr + it * 32;
                *(uint2*)(Bn + (size_t)r * HS2 + lq * 4) =
                    make_uint2(f2h2u(pw[it].x, pw[it].y), f2h2u(pw[it].z, pw[it].w));
            }
        }
        __syncthreads();
    }

#pragma unroll
    for (int nt = 0; nt < 4; ++nt) {
        int col = n0 + CB + nt * 8 + 2 * c;
        float2 bb = *(const float2*)(bd + col);
#pragma unroll
        for (int mt = 0; mt < 2; ++mt) {
            int row0 = m0 + RB + mt * 16 + g;
            if (row0 < M)
                *(__half2*)(Cd + (size_t)row0 * G3 + col) =
                    __floats2half2_rn(acc[mt][nt][0] + bb.x, acc[mt][nt][1] + bb.y);
            int row1 = row0 + 8;
            if (row1 < M)
                *(__half2*)(Cd + (size_t)row1 * G3 + col) =
                    __floats2half2_rn(acc[mt][nt][2] + bb.x, acc[mt][nt][3] + bb.y);
        }
    }
}

// ---------------- persistent fused GRU scan (fp16 MMA, 128x32 tile, 32-k chunks) ----------------
// H dual-stored: fp32 (carry + epilogue) and fp16 (MMA operand). MMA staging
// reads the fp16 mirror -> half the dominant L2 read stream, zero cvt in loop.
__global__ __launch_bounds__(256, 2)
void gru_scan(float* __restrict__ H0, float* __restrict__ H1,
              __half* __restrict__ H0H, __half* __restrict__ H1H,
              const float* __restrict__ Whh,    // [2][768][256]
              const float* __restrict__ bhh,    // [2][768]
              const __half* __restrict__ GX,    // [2][N*T][768] or nullptr
              const __half* __restrict__ PV,    // [2][VOCAB][768] or nullptr
              const int*   __restrict__ tok,    // tokens or nullptr
              int N, int T, int barBase)
{
    extern __shared__ __half smemh[];
    __half* Wres = smemh;                        // [96][WH] rows: gt*32 + j
    __half* Hsm  = smemh + 96 * WH;              // [2][128][HS2]

    int d  = blockIdx.z;
    int n0 = blockIdx.x * 128;
    int j0 = blockIdx.y * 32;
    int bid = barBase + d * gridDim.x + blockIdx.x;

    const float* Wd = Whh + (size_t)d * G3 * HD;

    int tid = threadIdx.x, lane = tid & 31, wid = tid >> 5;
    int wm = wid & 1, wn = wid >> 1;
    int RB = wm * 64, CB = wn * 8;
    int g = lane >> 2, c = lane & 3;

    // ---- load resident W slice (fp16 RN once): 96 rows x 256 cols ----
    for (int idx = tid; idx < 96 * 64; idx += 256) {
        int row = idx >> 6;
        int c4  = idx & 63;
        int gt = row >> 5, j = row & 31;
        float4 v = *(const float4*)(Wd + (size_t)(gt * 256 + j0 + j) * HD + c4 * 4);
        *(uint2*)(Wres + (size_t)row * WH + c4 * 4) =
            make_uint2(f2h2u(v.x, v.y), f2h2u(v.z, v.w));
    }
    __syncthreads();

    int l7 = lane & 7, ts = lane >> 3;
    unsigned sH = (unsigned)__cvta_generic_to_shared(Hsm);
    unsigned sW = (unsigned)__cvta_generic_to_shared(Wres);

    unsigned aAddr[4];
#pragma unroll
    for (int mt = 0; mt < 4; ++mt)
        aAddr[mt] = sH + (unsigned)(((RB + mt * 16 + l7 + (ts & 1) * 8) * HS2
                                     + (ts >> 1) * 8) * 2);
    unsigned bAddr01 = sW + (unsigned)((((ts >> 1) * 32 + CB + l7) * WH + (ts & 1) * 8) * 2);
    unsigned bAddr2  = sW + (unsigned)(((64 + CB + l7) * WH + (ts & 1) * 8) * 2);

    bool is64 = false;
    if (tok) is64 = (tok[1] == 0) & (tok[3] == 0) & (tok[5] == 0) & (tok[7] == 0);

    int cc = j0 + CB + 2 * c;
    float2 br2 = *(const float2*)(bhh + (size_t)d * G3 + cc);
    float2 bz2 = *(const float2*)(bhh + (size_t)d * G3 + 256 + cc);
    float2 bn2 = *(const float2*)(bhh + (size_t)d * G3 + 512 + cc);

    // staging: wm-group (128 threads) stages rows [wm*64, +64), 4 iters of 16 rows;
    // per-thread granule = 8B (4 halfs) from the fp16 H mirror
    int gid = wn * 32 + lane;
    int srow0 = wm * 64 + (gid >> 3);   // + it*16
    int sq = gid & 7;
    int barId = wm + 1;

    int rowi[8];
#pragma unroll
    for (int idx = 0; idx < 8; ++idx) {
        int mt = idx >> 1, half = idx & 1;
        rowi[idx] = n0 + RB + mt * 16 + g + half * 8;
    }

    for (int t = 0; t < T; ++t) {
        const float*  Hin   = (t & 1) ? H1  : H0;
        float*        Hout  = (t & 1) ? H0  : H1;
        const __half* HinH  = (t & 1) ? H1H : H0H;
        __half*       HoutH = (t & 1) ? H0H : H1H;
        int teff = d ? (T - 1 - t) : t;

        const __half* gxp[8];
#pragma unroll
        for (int idx = 0; idx < 8; ++idx) {
            int r = rowi[idx];
            if (r < N) {
                if (tok) {
                    int ti = r * T + teff;
                    int tv = is64 ? tok[2 * (size_t)ti] : tok[ti];
                    gxp[idx] = PV + ((size_t)d * VOCAB + tv) * G3;
                } else {
                    gxp[idx] = GX + ((size_t)d * N * T + (size_t)r * T + teff) * G3;
                }
            } else gxp[idx] = PV ? PV : GX;
        }

        float acc[3][4][4];
#pragma unroll
        for (int i = 0; i < 3; ++i)
#pragma unroll
            for (int j = 0; j < 4; ++j)
#pragma unroll
                for (int k = 0; k < 4; ++k) acc[i][j][k] = 0.f;

        if (t > 0) {   // step 0: Hin == 0 -> Gh == 0
            const __half* Hb = HinH + (size_t)d * N * HD;
            uint2 ph[4];
#pragma unroll
            for (int it = 0; it < 4; ++it) {
                int rl = srow0 + it * 16;
                ph[it] = make_uint2(0u, 0u);
                if (n0 + rl < N)
                    ph[it] = *(const uint2*)(Hb + (size_t)(n0 + rl) * HD + sq * 4);
            }

            for (int k0i = 0; k0i < 8; ++k0i) {
                __half* buf = Hsm + (size_t)(k0i & 1) * 128 * HS2;
#pragma unroll
                for (int it = 0; it < 4; ++it)
                    *(uint2*)(buf + (size_t)(srow0 + it * 16) * HS2 + sq * 4) = ph[it];
                barhalf(barId);

                if (k0i < 7) {
                    int k0 = (k0i + 1) * 32;
#pragma unroll
                    for (int it = 0; it < 4; ++it) {
                        int rl = srow0 + it * 16;
                        ph[it] = make_uint2(0u, 0u);
                        if (n0 + rl < N)
                            ph[it] = *(const uint2*)(Hb + (size_t)(n0 + rl) * HD + k0 + sq * 4);
                    }
                }

                unsigned hbuf = (unsigned)((k0i & 1) * 128 * HS2 * 2);
                unsigned kwo  = (unsigned)(k0i * 64);   // 32 halfs per chunk in W
#pragma unroll
                for (int ks = 0; ks < 2; ++ks) {
                    unsigned kbo = (unsigned)(ks * 32); // 16 halfs
                    unsigned a[4][4];
#pragma unroll
                    for (int mt = 0; mt < 4; ++mt)
                        ldsm4(a[mt][0], a[mt][1], a[mt][2], a[mt][3],
                              aAddr[mt] + hbuf + kbo);
                    unsigned b00, b01, b10, b11, b20, b21;
                    ldsm4(b00, b01, b10, b11, bAddr01 + kwo + kbo);
                    ldsm2(b20, b21, bAddr2 + kwo + kbo);
#pragma unroll
                    for (int mt = 0; mt < 4; ++mt) {
                        mma16(acc[0][mt], a[mt][0], a[mt][1], a[mt][2], a[mt][3], b00, b01);
                        mma16(acc[1][mt], a[mt][0], a[mt][1], a[mt][2], a[mt][3], b10, b11);
                        mma16(acc[2][mt], a[mt][0], a[mt][1], a[mt][2], a[mt][3], b20, b21);
                    }
                }
            }
        }

        // ---- gate math epilogue: 8 instances in 2 phases of 4 ----
#pragma unroll
        for (int phx = 0; phx < 2; ++phx) {
            float2 GR[4], GZ[4], GN[4], HH[4];
            bool val[4];
#pragma unroll
            for (int i = 0; i < 4; ++i) {
                int idx = phx * 4 + i;
                int r = rowi[idx];
                val[i] = (r < N);
                GR[i] = GZ[i] = GN[i] = HH[i] = make_float2(0.f, 0.f);
                if (val[i]) {
                    const __half* gxrow = gxp[idx];
                    GR[i] = __half22float2(*(const __half2*)(gxrow + cc));
                    GZ[i] = __half22float2(*(const __half2*)(gxrow + 256 + cc));
                    GN[i] = __half22float2(*(const __half2*)(gxrow + 512 + cc));
                    if (t > 0) HH[i] = *(const float2*)(Hin + (size_t)(d * N + r) * HD + cc);
                }
            }
#pragma unroll
            for (int i = 0; i < 4; ++i) {
                if (!val[i]) continue;
                int idx = phx * 4 + i;
                int mt = idx >> 1, half = idx & 1;
                float aR0 = acc[0][mt][half * 2 + 0], aR1 = acc[0][mt][half * 2 + 1];
                float aZ0 = acc[1][mt][half * 2 + 0], aZ1 = acc[1][mt][half * 2 + 1];
                float aN0 = acc[2][mt][half * 2 + 0], aN1 = acc[2][mt][half * 2 + 1];

                float r0 = fsigm(GR[i].x + aR0 + br2.x);
                float r1 = fsigm(GR[i].y + aR1 + br2.y);
                float z0 = fsigm(GZ[i].x + aZ0 + bz2.x);
                float z1 = fsigm(GZ[i].y + aZ1 + bz2.y);
                float n0v = ftanh(GN[i].x + r0 * (aN0 + bn2.x));
                float n1v = ftanh(GN[i].y + r1 * (aN1 + bn2.y));

                float2 o;
                o.x = n0v + z0 * (HH[i].x - n0v);
                o.y = n1v + z1 * (HH[i].y - n1v);
                size_t off = (size_t)(d * N + rowi[idx]) * HD + cc;
                *(float2*)(Hout + off) = o;
                *(__half2*)(HoutH + off) = __floats2half2_rn(o.x, o.y);
            }
        }

        if (t + 1 < T) gbar(bid, gridDim.y, (unsigned)(t + 1));
    }
}

// ---------------- FC head: Linear(256->128) -> SELU -> Linear(128->1) on (X+X2) ----------------
__global__ void fc_head(const float* __restrict__ X, const float* __restrict__ X2,
                        const float* __restrict__ W1, const float* __restrict__ b1,
                        const float* __restrict__ W2, const float* __restrict__ b2,
                        float* __restrict__ out)
{
    int row = blockIdx.x;
    int h = threadIdx.x;  // 128 threads
    const float* x  = X  + (size_t)row * HD;
    const float* x2 = X2 + (size_t)row * HD;
    const float* w  = W1 + (size_t)h * HD;
    float s = 0.f;
#pragma unroll 8
    for (int k = 0; k < HD; k += 4) {
        float4 xv = *(const float4*)(x + k);
        float4 yv = *(const float4*)(x2 + k);
        float4 wv = *(const float4*)(w + k);
        s += (xv.x + yv.x) * wv.x + (xv.y + yv.y) * wv.y
           + (xv.z + yv.z) * wv.z + (xv.w + yv.w) * wv.w;
    }
    s += b1[h];
    const float SC = 1.0507009873554805f, AL = 1.6732632423543772f;
    float selu = SC * (s > 0.f ? s : AL * expm1f(s));
    float v = selu * W2[h];
    __shared__ float red[128];
    red[h] = v; __syncthreads();
    for (int st = 64; st > 0; st >>= 1) {
        if (h < st) red[h] += red[h + st];
        __syncthreads();
    }
    if (h == 0) out[row] = red[0] + b2[0];
}

// ---------------- launch ----------------
extern "C" void kernel_launch(void* const* d_in, const int* in_sizes, int n_in,
                              void* d_out, int out_size)
{
    const int*   tok   = (const int*)  d_in[0];
    const float* emb   = (const float*)d_in[1];
    const float* wWih  = (const float*)d_in[2];
    const float* wWhh  = (const float*)d_in[3];
    const float* wbih  = (const float*)d_in[4];
    const float* wbhh  = (const float*)d_in[5];
    const float* sWih  = (const float*)d_in[6];
    const float* sWhh  = (const float*)d_in[7];
    const float* sbih  = (const float*)d_in[8];
    const float* sbhh  = (const float*)d_in[9];
    const float* rWih  = (const float*)d_in[10];
    const float* rWhh  = (const float*)d_in[11];
    const float* rbih  = (const float*)d_in[12];
    const float* rbhh  = (const float*)d_in[13];
    const float* rfcW1 = (const float*)d_in[14];
    const float* rfcb1 = (const float*)d_in[15];
    const float* rfcW2 = (const float*)d_in[16];
    const float* rfcb2 = (const float*)d_in[17];
    const float* pfcW1 = (const float*)d_in[18];
    const float* pfcb1 = (const float*)d_in[19];
    const float* pfcW2 = (const float*)d_in[20];
    const float* pfcb2 = (const float*)d_in[21];
    float* out = (float*)d_out;

    static bool attr_set = false;
    if (!attr_set) {
        cudaFuncSetAttribute(gru_scan, cudaFuncAttributeMaxDynamicSharedMemorySize,
                             SCAN_SMEM_BYTES);
        cudaFuncSetAttribute(gemm_proj_mma, cudaFuncAttributeMaxDynamicSharedMemorySize,
                             GEMM_SMEM_BYTES);
        cudaFuncSetAttribute(gemm_proj_h, cudaFuncAttributeMaxDynamicSharedMemorySize,
                             GEMM_SMEM_BYTES);
        attr_set = true;
    }

    __half *pv, *gxs, *gxr, *eh, *wih16, *hwHB, *hsHB, *hrHB;
    float *hwB, *hsB, *hrB;
    cudaGetSymbolAddress((void**)&pv,    g_PV);
    cudaGetSymbolAddress((void**)&gxs,   g_GXs);
    cudaGetSymbolAddress((void**)&gxr,   g_GXr);
    cudaGetSymbolAddress((void**)&eh,    g_EH);
    cudaGetSymbolAddress((void**)&wih16, g_WIH);
    cudaGetSymbolAddress((void**)&hwB,   g_Hw);
    cudaGetSymbolAddress((void**)&hsB,   g_Hs);
    cudaGetSymbolAddress((void**)&hrB,   g_Hr);
    cudaGetSymbolAddress((void**)&hwHB,  g_HwH);
    cudaGetSymbolAddress((void**)&hsHB,  g_HsH);
    cudaGetSymbolAddress((void**)&hrHB,  g_HrH);

    float*  hw1  = hwB  + (size_t)2 * NW * HD;
    float*  hs1  = hsB  + (size_t)2 * NS * HD;
    float*  hr1  = hrB  + (size_t)2 * NR * HD;
    __half* hwH1 = hwHB + (size_t)2 * NW * HD;
    __half* hsH1 = hsHB + (size_t)2 * NS * HD;
    __half* hrH1 = hrHB + (size_t)2 * NR * HD;

    kinit_bar<<<1, 1024>>>();

    // pre-convert emb and word Wih to fp16
    cvt16<<<512, 256>>>(emb,  eh,    (size_t)VOCAB * HD);
    cvt16<<<64,  256>>>(wWih, wih16, (size_t)2 * G3 * HD);

    // project full vocabulary once per direction (pure fp16 inputs)
    gemm_proj_h<<<dim3((VOCAB + 127) / 128, G3 / 64, 2), 256, GEMM_SMEM_BYTES>>>(
        eh, VOCAB, wih16, wbih, pv);

    // word-level scan (T=32)
    gru_scan<<<dim3(NW / 128, 8, 2), 256, SCAN_SMEM_BYTES>>>(
        hwB, hw1, hwHB, hwH1, wWhh, wbhh, nullptr, pv, tok, NW, TW, 0);
    float* hwF = (TW & 1) ? hw1 : hwB;

    // sentence-level: project (hf+hb fused) + scan (T=16)
    gemm_proj_mma<<<dim3((NW + 127) / 128, G3 / 64, 2), 256, GEMM_SMEM_BYTES>>>(
        hwF, hwF + (size_t)NW * HD, NW, sWih, sbih, gxs);
    gru_scan<<<dim3(1, 8, 2), 256, SCAN_SMEM_BYTES>>>(
        hsB, hs1, hsHB, hsH1, sWhh, sbhh, gxs, nullptr, nullptr, NS, TS, 32);
    float* hsF = (TS & 1) ? hs1 : hsB;

    // review-star head -> out[8..135]
    fc_head<<<NS, 128>>>(hsF, hsF + (size_t)NS * HD, rfcW1, rfcb1, rfcW2, rfcb2, out + NR);

    // review-level (business) biGRU: project (fused sum) + scan (T=16)
    gemm_proj_mma<<<dim3(1, G3 / 64, 2), 256, GEMM_SMEM_BYTES>>>(
        hsF, hsF + (size_t)NS * HD, NS, rWih, rbih, gxr);
    gru_scan<<<dim3(1, 8, 2), 256, SCAN_SMEM_BYTES>>>(
        hrB, hr1, hrHB, hrH1, rWhh, rbhh, gxr, nullptr, nullptr, NR, TR, 34);
    float* hrF = (TR & 1) ? hr1 : hrB;

    // business head -> out[0..7]
    fc_head<<<NR, 128>>>(hrF, hrF + (size_t)NR * HD, pfcW1, pfcb1, pfcW2, pfcb2, out);

    (void)in_sizes; (void)n_in; (void)out_size;
}